// round 4
// baseline (speedup 1.0000x reference)
#include <cuda_runtime.h>
#include <cuda_bf16.h>
#include <math.h>

#define NA 25000
#define NE 200000
#define FF 128

// ---------------- static scratch ----------------
__device__ float g_phiS[(size_t)NE * 21];
__device__ float g_dir[(size_t)NE * 3];
__device__ int   g_js[NE];
__device__ int   g_eo[NE];
__device__ int   g_cnt[NA];
__device__ int   g_start[NA + 1];
__device__ int   g_cursor[NA];
__device__ float g_fWX[21 * 1152];
__device__ float g_q[(size_t)NA * 128];
__device__ float g_h[(size_t)NA * 128];
__device__ float g_x[(size_t)NA * 384];
__device__ float g_muA[(size_t)NA * 384];
__device__ float g_muB[(size_t)NA * 384];
__device__ float g_mm[(size_t)NA * 768];
__device__ float g_ctx[(size_t)NA * 256];
__device__ float g_s[(size_t)NA * 128];
__device__ float g_filt[(size_t)NE * 384];

// ---------------- prep kernels ----------------
__global__ void k_fwx(const float* __restrict__ fW, const float* __restrict__ fb) {
    int c = blockIdx.x * blockDim.x + threadIdx.x;
    if (c >= 1152) return;
    for (int k = 0; k < 20; k++) g_fWX[k * 1152 + c] = fW[k * 1152 + c];
    g_fWX[20 * 1152 + c] = fb[c];
}

__global__ void k_count(const int* __restrict__ idx_i) {
    int e = blockIdx.x * blockDim.x + threadIdx.x;
    if (e < NE) atomicAdd(&g_cnt[idx_i[e]], 1);
}

__global__ void k_scan() {
    __shared__ int sm[1024];
    __shared__ int carry_s;
    int tid = threadIdx.x;
    if (tid == 0) carry_s = 0;
    __syncthreads();
    for (int base = 0; base < NA; base += 1024) {
        int idx = base + tid;
        int v = (idx < NA) ? g_cnt[idx] : 0;
        sm[tid] = v;
        __syncthreads();
        for (int off = 1; off < 1024; off <<= 1) {
            int t = (tid >= off) ? sm[tid - off] : 0;
            __syncthreads();
            sm[tid] += t;
            __syncthreads();
        }
        int out = carry_s + sm[tid] - v;
        if (idx < NA) { g_start[idx] = out; g_cursor[idx] = out; }
        int tot = sm[1023];
        __syncthreads();
        if (tid == 0) carry_s += tot;
        __syncthreads();
    }
    if (tid == 0) g_start[NA] = carry_s;
}

__global__ void k_build(const float* __restrict__ pos,
                        const int* __restrict__ idx_i,
                        const int* __restrict__ idx_j) {
    int e = blockIdx.x * blockDim.x + threadIdx.x;
    if (e >= NE) return;
    int i = idx_i[e], j = idx_j[e];
    float r0 = pos[3 * j + 0] - pos[3 * i + 0];
    float r1 = pos[3 * j + 1] - pos[3 * i + 1];
    float r2 = pos[3 * j + 2] - pos[3 * i + 2];
    r0 = (fabsf(r0) < 1e-6f) ? 1e-6f : r0;
    r1 = (fabsf(r1) < 1e-6f) ? 1e-6f : r1;
    r2 = (fabsf(r2) < 1e-6f) ? 1e-6f : r2;
    float d = sqrtf(r0 * r0 + r1 * r1 + r2 * r2);
    float inv = 1.0f / d;
    float fc = (d < 5.0f) ? 0.5f * (cosf(0.628318530717959f * d) + 1.0f) : 0.0f;
    int slot = atomicAdd(&g_cursor[i], 1);
    g_js[slot] = j;
    g_eo[slot] = e;
    g_dir[3 * slot + 0] = r0 * inv;
    g_dir[3 * slot + 1] = r1 * inv;
    g_dir[3 * slot + 2] = r2 * inv;
    const float step = 5.0f / 19.0f;
    const float coeff = -7.22f;  // -0.5/(5/19)^2
    size_t pb = (size_t)slot * 21;
    for (int k = 0; k < 20; k++) {
        float df = d - (float)k * step;
        g_phiS[pb + k] = expf(coeff * df * df) * fc;
    }
    g_phiS[pb + 20] = fc;
}

__global__ void k_init_q(const int* __restrict__ z, const float* __restrict__ emb) {
    int n = blockIdx.x;
    int f = threadIdx.x;
    g_q[(size_t)n * 128 + f] = emb[(size_t)z[n] * 128 + f];
}

// ---------------- generic tiled fp32 GEMM ----------------
// C[M,Nc] = act(A[M,K] @ B[K,Nc] + bias), row-major. ldb for B slicing.
#define BM 64
#define BN 64
#define BK 16
__global__ void __launch_bounds__(256) k_gemm(const float* __restrict__ A,
                                              const float* __restrict__ B,
                                              const float* __restrict__ bias,
                                              float* __restrict__ C,
                                              int M, int K, int Nc, int ldb, int act) {
    __shared__ float As[BK][BM];
    __shared__ float Bs[BK][BN];
    int m0 = blockIdx.y * BM, n0 = blockIdx.x * BN;
    int tid = threadIdx.x;
    int tx = tid & 15, ty = tid >> 4;
    int la_r = tid >> 2;          // 0..63
    int la_k = (tid & 3) * 4;     // 0,4,8,12
    int lb_k = tid >> 4;          // 0..15
    int lb_n = (tid & 15) * 4;    // 0..60
    float acc[4][4];
#pragma unroll
    for (int i = 0; i < 4; i++)
#pragma unroll
        for (int jj = 0; jj < 4; jj++) acc[i][jj] = 0.0f;

    for (int kb = 0; kb < K; kb += BK) {
        int m = m0 + la_r;
#pragma unroll
        for (int u = 0; u < 4; u++) {
            int k = kb + la_k + u;
            As[la_k + u][la_r] = (k < K && m < M) ? A[(size_t)m * K + k] : 0.0f;
        }
        int kB = kb + lb_k;
#pragma unroll
        for (int u = 0; u < 4; u++) {
            int n = n0 + lb_n + u;
            Bs[lb_k][lb_n + u] = (kB < K && n < Nc) ? B[(size_t)kB * ldb + n] : 0.0f;
        }
        __syncthreads();
#pragma unroll
        for (int k = 0; k < BK; k++) {
            float4 a = *(const float4*)&As[k][ty * 4];
            float4 b = *(const float4*)&Bs[k][tx * 4];
            acc[0][0] += a.x * b.x; acc[0][1] += a.x * b.y; acc[0][2] += a.x * b.z; acc[0][3] += a.x * b.w;
            acc[1][0] += a.y * b.x; acc[1][1] += a.y * b.y; acc[1][2] += a.y * b.z; acc[1][3] += a.y * b.w;
            acc[2][0] += a.z * b.x; acc[2][1] += a.z * b.y; acc[2][2] += a.z * b.z; acc[2][3] += a.z * b.w;
            acc[3][0] += a.w * b.x; acc[3][1] += a.w * b.y; acc[3][2] += a.w * b.z; acc[3][3] += a.w * b.w;
        }
        __syncthreads();
    }
#pragma unroll
    for (int i = 0; i < 4; i++) {
        int m = m0 + ty * 4 + i;
        if (m >= M) continue;
#pragma unroll
        for (int jj = 0; jj < 4; jj++) {
            int n = n0 + tx * 4 + jj;
            if (n >= Nc) continue;
            float c = acc[i][jj];
            if (bias) c += bias[n];
            if (act) c = c * (1.0f / (1.0f + __expf(-c)));
            C[(size_t)m * Nc + n] = c;
        }
    }
}

// ---------------- edge aggregation (one block per atom, deterministic) ----------------
#define MAXD 512
__global__ void __launch_bounds__(128) k_edge() {
    int i = blockIdx.x;
    int f = threadIdx.x;
    int s0 = g_start[i], s1 = g_start[i + 1];
    int L = s1 - s0;
    __shared__ int se[MAXD];
    __shared__ int ord[MAXD];
    bool srt = (L <= MAXD);
    if (srt && L > 0) {
        for (int a = f; a < L; a += 128) se[a] = g_eo[s0 + a];
        __syncthreads();
        for (int a = f; a < L; a += 128) {
            int my = se[a];
            int r = 0;
            for (int b = 0; b < L; b++) r += (se[b] < my);
            ord[r] = a;
        }
        __syncthreads();
    }
    float aq = 0.0f, m0 = 0.0f, m1 = 0.0f, m2 = 0.0f;
    for (int a = 0; a < L; a++) {
        int slot = s0 + (srt ? ord[a] : a);
        int j = g_js[slot];
        float d0 = g_dir[3 * slot + 0];
        float d1 = g_dir[3 * slot + 1];
        float d2 = g_dir[3 * slot + 2];
        size_t fbx = (size_t)slot * 384;
        float fq = g_filt[fbx + f];
        float fR = g_filt[fbx + 128 + f];
        float fM = g_filt[fbx + 256 + f];
        size_t xb = (size_t)j * 384;
        float xq = g_x[xb + f];
        float xR = g_x[xb + 128 + f];
        float xM = g_x[xb + 256 + f];
        float mj0 = g_muA[xb + f];
        float mj1 = g_muA[xb + 128 + f];
        float mj2 = g_muA[xb + 256 + f];
        aq += fq * xq;
        float tR = fR * xR, tM = fM * xM;
        m0 += tR * d0 + tM * mj0;
        m1 += tR * d1 + tM * mj1;
        m2 += tR * d2 + tM * mj2;
    }
    size_t qb = (size_t)i * 128 + f;
    size_t mb_ = (size_t)i * 384;
    g_q[qb] += aq;
    g_muB[mb_ + f]       = g_muA[mb_ + f]       + m0;
    g_muB[mb_ + 128 + f] = g_muA[mb_ + 128 + f] + m1;
    g_muB[mb_ + 256 + f] = g_muA[mb_ + 256 + f] + m2;
}

// ---------------- mixing elementwise kernels ----------------
__global__ void k_ctx() {
    int n = blockIdx.x;
    int f = threadIdx.x;
    size_t mmb = (size_t)n * 768;
    float v0 = g_mm[mmb + f];
    float v1 = g_mm[mmb + 256 + f];
    float v2 = g_mm[mmb + 512 + f];
    float w0 = g_mm[mmb + 128 + f];
    float w1 = g_mm[mmb + 384 + f];
    float w2 = g_mm[mmb + 640 + f];
    float vn = sqrtf(v0 * v0 + v1 * v1 + v2 * v2 + 1e-8f);
    float s = v0 * w0 + v1 * w1 + v2 * w2;
    g_ctx[(size_t)n * 256 + f] = g_q[(size_t)n * 128 + f];
    g_ctx[(size_t)n * 256 + 128 + f] = vn;
    g_s[(size_t)n * 128 + f] = s;
}

__global__ void k_update() {
    int n = blockIdx.x;
    int f = threadIdx.x;
    size_t xb = (size_t)n * 384;
    float dq  = g_x[xb + f];
    float dmc = g_x[xb + 128 + f];
    float dqm = g_x[xb + 256 + f];
    g_q[(size_t)n * 128 + f] += dq + dqm * g_s[(size_t)n * 128 + f];
    size_t mmb = (size_t)n * 768;
    g_muA[xb + f]       = g_muB[xb + f]       + dmc * g_mm[mmb + 128 + f];
    g_muA[xb + 128 + f] = g_muB[xb + 128 + f] + dmc * g_mm[mmb + 384 + f];
    g_muA[xb + 256 + f] = g_muB[xb + 256 + f] + dmc * g_mm[mmb + 640 + f];
}

// ---------------- launcher ----------------
extern "C" void kernel_launch(void* const* d_in, const int* in_sizes, int n_in,
                              void* d_out, int out_size) {
    const int*   z     = (const int*)d_in[0];
    const float* pos   = (const float*)d_in[1];
    const int*   idx_i = (const int*)d_in[2];
    const int*   idx_j = (const int*)d_in[3];
    const float* emb   = (const float*)d_in[4];
    const float* fW    = (const float*)d_in[5];
    const float* fb    = (const float*)d_in[6];
    const float* iW1   = (const float*)d_in[7];
    const float* ib1   = (const float*)d_in[8];
    const float* iW2   = (const float*)d_in[9];
    const float* ib2   = (const float*)d_in[10];
    const float* mWmix = (const float*)d_in[11];
    const float* mW1   = (const float*)d_in[12];
    const float* mb1   = (const float*)d_in[13];
    const float* mW2   = (const float*)d_in[14];
    const float* mb2   = (const float*)d_in[15];
    float* out = (float*)d_out;

    void *p_cnt, *p_muA, *p_q, *p_h, *p_x, *p_muB, *p_mm, *p_ctx, *p_phiS, *p_fWX, *p_filt;
    cudaGetSymbolAddress(&p_cnt, g_cnt);
    cudaGetSymbolAddress(&p_muA, g_muA);
    cudaGetSymbolAddress(&p_q, g_q);
    cudaGetSymbolAddress(&p_h, g_h);
    cudaGetSymbolAddress(&p_x, g_x);
    cudaGetSymbolAddress(&p_muB, g_muB);
    cudaGetSymbolAddress(&p_mm, g_mm);
    cudaGetSymbolAddress(&p_ctx, g_ctx);
    cudaGetSymbolAddress(&p_phiS, g_phiS);
    cudaGetSymbolAddress(&p_fWX, g_fWX);
    cudaGetSymbolAddress(&p_filt, g_filt);

    cudaMemsetAsync(p_cnt, 0, NA * sizeof(int));
    cudaMemsetAsync(p_muA, 0, (size_t)NA * 384 * sizeof(float));

    k_fwx<<<(1152 + 127) / 128, 128>>>(fW, fb);
    k_count<<<(NE + 255) / 256, 256>>>(idx_i);
    k_scan<<<1, 1024>>>();
    k_build<<<(NE + 127) / 128, 128>>>(pos, idx_i, idx_j);
    k_init_q<<<NA, 128>>>(z, emb);

    const float* fq = (const float*)p_q;
    const float* fh = (const float*)p_h;
    const float* fx = (const float*)p_x;
    const float* fmuB = (const float*)p_muB;
    const float* fmm = (const float*)p_mm;
    const float* fctx = (const float*)p_ctx;
    const float* fphiS = (const float*)p_phiS;
    const float* ffWX = (const float*)p_fWX;

    int gy_a = (NA + BM - 1) / BM;      // 391
    int gy_e = (NE + BM - 1) / BM;      // 3125
    int gy_m = (NA * 3 + BM - 1) / BM;  // 1172

    for (int t = 0; t < 3; t++) {
        // H1 = silu(Q @ iW1[t] + ib1[t])   [NA,128]
        k_gemm<<<dim3(2, gy_a), 256>>>(fq, iW1 + (size_t)t * 128 * 128, ib1 + t * 128,
                                       (float*)p_h, NA, 128, 128, 128, 1);
        // X = H1 @ iW2[t] + ib2[t]          [NA,384]
        k_gemm<<<dim3(6, gy_a), 256>>>(fh, iW2 + (size_t)t * 128 * 384, ib2 + t * 384,
                                       (float*)p_x, NA, 128, 384, 384, 0);
        // FILT = phiS @ fWX[:, t*384:(t+1)*384]   [NE,384]
        k_gemm<<<dim3(6, gy_e), 256>>>(fphiS, ffWX + t * 384, nullptr,
                                       (float*)p_filt, NE, 21, 384, 1152, 0);
        // edge aggregation: q += dq ; muB = muA + dmu
        k_edge<<<NA, 128>>>();
        // MUMIX = muB(as [3N,128]) @ mWmix[t]    [3N,256]
        k_gemm<<<dim3(4, gy_m), 256>>>(fmuB, mWmix + (size_t)t * 128 * 256, nullptr,
                                       (float*)p_mm, NA * 3, 128, 256, 256, 0);
        // ctx / Vn / s
        k_ctx<<<NA, 128>>>();
        // H2 = silu(CTX @ mW1[t] + mb1[t])   [NA,128], K=256
        k_gemm<<<dim3(2, gy_a), 256>>>(fctx, mW1 + (size_t)t * 256 * 128, mb1 + t * 128,
                                       (float*)p_h, NA, 256, 128, 128, 1);
        // X2 = H2 @ mW2[t] + mb2[t]           [NA,384]
        k_gemm<<<dim3(6, gy_a), 256>>>(fh, mW2 + (size_t)t * 128 * 384, mb2 + t * 384,
                                       (float*)p_x, NA, 128, 384, 384, 0);
        // final per-atom update: q, muA
        k_update<<<NA, 128>>>();
    }

    cudaMemcpyAsync(out, p_q, (size_t)NA * 128 * sizeof(float), cudaMemcpyDeviceToDevice);
    cudaMemcpyAsync(out + (size_t)NA * 128, p_muA, (size_t)NA * 384 * sizeof(float),
                    cudaMemcpyDeviceToDevice);
}

// round 8
// speedup vs baseline: 1.3525x; 1.3525x over previous
#include <cuda_runtime.h>
#include <cuda_bf16.h>
#include <mma.h>
#include <math.h>
#include <stdint.h>

using namespace nvcuda;

#define NA 25000
#define NE 200000

// ---------------- static scratch ----------------
__device__ float g_phiS[(size_t)NE * 21];
__device__ float g_dir[(size_t)NE * 3];
__device__ int   g_js[NE];
__device__ int   g_eo[NE];
__device__ int   g_cnt[NA];
__device__ int   g_start[NA + 1];
__device__ int   g_cursor[NA];
__device__ float g_fWX[21 * 1152];
__device__ float g_q[(size_t)NA * 128];
__device__ float g_x[(size_t)NA * 384];
__device__ float g_muA[(size_t)NA * 384];
__device__ float g_muB[(size_t)NA * 384];
__device__ float g_mm[(size_t)NA * 768];
__device__ float g_s[(size_t)NA * 128];
__device__ float g_filt[(size_t)NE * 384];
// bf16 hi/lo activation buffers ([M, 2K]: hi cols [0,K), lo cols [K,2K))
__device__ __nv_bfloat16 g_qhl[(size_t)NA * 256];
__device__ __nv_bfloat16 g_hhl[(size_t)NA * 256];
__device__ __nv_bfloat16 g_ctxhl[(size_t)NA * 512];
__device__ __nv_bfloat16 g_muBhl[(size_t)NA * 768];
// bf16 transposed+split weights ([N, 2K] per t)
__device__ __nv_bfloat16 g_WT1[3 * 128 * 256];
__device__ __nv_bfloat16 g_WT2[3 * 384 * 256];
__device__ __nv_bfloat16 g_WTmix[3 * 256 * 256];
__device__ __nv_bfloat16 g_WTm1[3 * 128 * 512];
__device__ __nv_bfloat16 g_WTm2[3 * 384 * 256];

// ---------------- wmma GEMM: C = act(A @ W^T + bias) ----------------
// A: [M, 2K] bf16 hi|lo.  W: [N, 2K] bf16 hi|lo (K-major).
// 3-term bf16x3: Ahi*Whi + Alo*Whi + Ahi*Wlo, fp32 accumulate.
// CTA tile 128x64, 8 warps (4x2), warp tile 32x32 (2x2 m16n16k16), BK=32.
#define PAD 40
__global__ void __launch_bounds__(256) k_wgemm(
    const __nv_bfloat16* __restrict__ A, const __nv_bfloat16* __restrict__ W,
    const float* __restrict__ bias, float* __restrict__ Cf,
    __nv_bfloat16* __restrict__ Chl, int M, int K, int N, int act) {
    extern __shared__ char smem[];
    __nv_bfloat16* As = (__nv_bfloat16*)smem;                 // [128][PAD]
    __nv_bfloat16* Bs = (__nv_bfloat16*)(smem + 128 * PAD * 2);  // [64][PAD]
    int tid = threadIdx.x;
    int wid = tid >> 5;
    int m0 = blockIdx.x * 128, n0 = blockIdx.y * 64;
    int lda = 2 * K;
    int wm = wid & 3, wn = wid >> 2;

    wmma::fragment<wmma::accumulator, 16, 16, 16, float> acc[2][2];
#pragma unroll
    for (int i = 0; i < 2; i++)
#pragma unroll
        for (int j = 0; j < 2; j++) wmma::fill_fragment(acc[i][j], 0.0f);

    int kchunks = K >> 5;
    int ksteps = 3 * kchunks;
    for (int step = 0; step < ksteps; step++) {
        int ph = step / kchunks, kb = step % kchunks;
        int ka = (ph == 1 ? K : 0) + kb * 32;
        int kw = (ph == 2 ? K : 0) + kb * 32;
        // load A tile [128 x 32]: 512 uint4, 2/thread
#pragma unroll
        for (int u = 0; u < 2; u++) {
            int idx = tid + u * 256;
            int r = idx >> 2, c8 = idx & 3;
            uint4 v = make_uint4(0, 0, 0, 0);
            int m = m0 + r;
            if (m < M) v = *(const uint4*)(A + (size_t)m * lda + ka + c8 * 8);
            *(uint4*)(As + r * PAD + c8 * 8) = v;
        }
        // load B tile [64 x 32]: 256 uint4, 1/thread
        {
            int r = tid >> 2, c8 = tid & 3;
            uint4 w = *(const uint4*)(W + (size_t)(n0 + r) * lda + kw + c8 * 8);
            *(uint4*)(Bs + r * PAD + c8 * 8) = w;
        }
        __syncthreads();
#pragma unroll
        for (int kk = 0; kk < 32; kk += 16) {
            wmma::fragment<wmma::matrix_a, 16, 16, 16, __nv_bfloat16, wmma::row_major> af[2];
            wmma::fragment<wmma::matrix_b, 16, 16, 16, __nv_bfloat16, wmma::col_major> bf[2];
#pragma unroll
            for (int i = 0; i < 2; i++)
                wmma::load_matrix_sync(af[i], As + (wm * 32 + i * 16) * PAD + kk, PAD);
#pragma unroll
            for (int j = 0; j < 2; j++)
                wmma::load_matrix_sync(bf[j], Bs + (wn * 32 + j * 16) * PAD + kk, PAD);
#pragma unroll
            for (int i = 0; i < 2; i++)
#pragma unroll
                for (int j = 0; j < 2; j++)
                    wmma::mma_sync(acc[i][j], af[i], bf[j], acc[i][j]);
        }
        __syncthreads();
    }

    // epilogue: stage fp32 [128x64] in smem, fuse bias/act, write out
    float* stg = (float*)smem;
#pragma unroll
    for (int i = 0; i < 2; i++)
#pragma unroll
        for (int j = 0; j < 2; j++)
            wmma::store_matrix_sync(stg + (wm * 32 + i * 16) * 64 + wn * 32 + j * 16,
                                    acc[i][j], 64, wmma::mem_row_major);
    __syncthreads();
#pragma unroll
    for (int u = 0; u < 8; u++) {
        int idx = tid + u * 256;
        int r = idx >> 4, c4 = (idx & 15) * 4;
        int m = m0 + r;
        if (m >= M) continue;
        float4 v = *(float4*)&stg[r * 64 + c4];
        int n = n0 + c4;
        if (bias) {
            v.x += bias[n + 0]; v.y += bias[n + 1];
            v.z += bias[n + 2]; v.w += bias[n + 3];
        }
        if (act) {
            v.x = v.x / (1.0f + __expf(-v.x));
            v.y = v.y / (1.0f + __expf(-v.y));
            v.z = v.z / (1.0f + __expf(-v.z));
            v.w = v.w / (1.0f + __expf(-v.w));
        }
        if (Cf) {
            *(float4*)(Cf + (size_t)m * N + n) = v;
        } else {
            __nv_bfloat16 h0 = __float2bfloat16(v.x), h1 = __float2bfloat16(v.y);
            __nv_bfloat16 h2 = __float2bfloat16(v.z), h3 = __float2bfloat16(v.w);
            __nv_bfloat16 l0 = __float2bfloat16(v.x - __bfloat162float(h0));
            __nv_bfloat16 l1 = __float2bfloat16(v.y - __bfloat162float(h1));
            __nv_bfloat16 l2 = __float2bfloat16(v.z - __bfloat162float(h2));
            __nv_bfloat16 l3 = __float2bfloat16(v.w - __bfloat162float(h3));
            __nv_bfloat16* ph = Chl + (size_t)m * 2 * N + n;
            *(__nv_bfloat162*)(ph + 0) = __nv_bfloat162(h0, h1);
            *(__nv_bfloat162*)(ph + 2) = __nv_bfloat162(h2, h3);
            __nv_bfloat16* pl = Chl + (size_t)m * 2 * N + N + n;
            *(__nv_bfloat162*)(pl + 0) = __nv_bfloat162(l0, l1);
            *(__nv_bfloat162*)(pl + 2) = __nv_bfloat162(l2, l3);
        }
    }
}
#define SMEM_WG 32768

// ---------------- prep kernels ----------------
__global__ void k_fwx(const float* __restrict__ fW, const float* __restrict__ fb) {
    int c = blockIdx.x * blockDim.x + threadIdx.x;
    if (c >= 1152) return;
    for (int k = 0; k < 20; k++) g_fWX[k * 1152 + c] = fW[k * 1152 + c];
    g_fWX[20 * 1152 + c] = fb[c];
}

// transpose [K,N] fp32 -> [N,2K] bf16 hi|lo, for 3 t's
__global__ void k_wsplit(const float* __restrict__ src, __nv_bfloat16* __restrict__ dst,
                         int K, int N) {
    int t = blockIdx.y;
    int id = blockIdx.x * 256 + threadIdx.x;
    if (id >= K * N) return;
    int k = id / N, n = id % N;
    float v = src[(size_t)t * K * N + (size_t)k * N + n];
    __nv_bfloat16 hi = __float2bfloat16(v);
    float lo = v - __bfloat162float(hi);
    size_t base = (size_t)t * N * 2 * K + (size_t)n * 2 * K;
    dst[base + k] = hi;
    dst[base + K + k] = __float2bfloat16(lo);
}

__global__ void k_count(const int* __restrict__ idx_i) {
    int e = blockIdx.x * blockDim.x + threadIdx.x;
    if (e < NE) atomicAdd(&g_cnt[idx_i[e]], 1);
}

__global__ void k_scan() {
    __shared__ int sm[1024];
    __shared__ int carry_s;
    int tid = threadIdx.x;
    if (tid == 0) carry_s = 0;
    __syncthreads();
    for (int base = 0; base < NA; base += 1024) {
        int idx = base + tid;
        int v = (idx < NA) ? g_cnt[idx] : 0;
        sm[tid] = v;
        __syncthreads();
        for (int off = 1; off < 1024; off <<= 1) {
            int t = (tid >= off) ? sm[tid - off] : 0;
            __syncthreads();
            sm[tid] += t;
            __syncthreads();
        }
        int out = carry_s + sm[tid] - v;
        if (idx < NA) { g_start[idx] = out; g_cursor[idx] = out; }
        int tot = sm[1023];
        __syncthreads();
        if (tid == 0) carry_s += tot;
        __syncthreads();
    }
    if (tid == 0) g_start[NA] = carry_s;
}

__global__ void k_build(const float* __restrict__ pos,
                        const int* __restrict__ idx_i,
                        const int* __restrict__ idx_j) {
    int e = blockIdx.x * blockDim.x + threadIdx.x;
    if (e >= NE) return;
    int i = idx_i[e], j = idx_j[e];
    float r0 = pos[3 * j + 0] - pos[3 * i + 0];
    float r1 = pos[3 * j + 1] - pos[3 * i + 1];
    float r2 = pos[3 * j + 2] - pos[3 * i + 2];
    r0 = (fabsf(r0) < 1e-6f) ? 1e-6f : r0;
    r1 = (fabsf(r1) < 1e-6f) ? 1e-6f : r1;
    r2 = (fabsf(r2) < 1e-6f) ? 1e-6f : r2;
    float d = sqrtf(r0 * r0 + r1 * r1 + r2 * r2);
    float inv = 1.0f / d;
    float fc = (d < 5.0f) ? 0.5f * (cosf(0.628318530717959f * d) + 1.0f) : 0.0f;
    int slot = atomicAdd(&g_cursor[i], 1);
    g_js[slot] = j;
    g_eo[slot] = e;
    g_dir[3 * slot + 0] = r0 * inv;
    g_dir[3 * slot + 1] = r1 * inv;
    g_dir[3 * slot + 2] = r2 * inv;
    const float step = 5.0f / 19.0f;
    const float coeff = -7.22f;
    size_t pb = (size_t)slot * 21;
    for (int k = 0; k < 20; k++) {
        float df = d - (float)k * step;
        g_phiS[pb + k] = expf(coeff * df * df) * fc;
    }
    g_phiS[pb + 20] = fc;
}

__global__ void k_init_q(const int* __restrict__ z, const float* __restrict__ emb) {
    int n = blockIdx.x;
    int f = threadIdx.x;
    float v = emb[(size_t)z[n] * 128 + f];
    g_q[(size_t)n * 128 + f] = v;
    __nv_bfloat16 hi = __float2bfloat16(v);
    g_qhl[(size_t)n * 256 + f] = hi;
    g_qhl[(size_t)n * 256 + 128 + f] = __float2bfloat16(v - __bfloat162float(hi));
}

// ---------------- scalar GEMM (FILT only: K=21) ----------------
#define BM 64
#define BN 64
#define BK 16
__global__ void __launch_bounds__(256) k_gemm(const float* __restrict__ A,
                                              const float* __restrict__ B,
                                              float* __restrict__ C,
                                              int M, int K, int Nc, int ldb) {
    __shared__ float As[BK][BM];
    __shared__ float Bs[BK][BN];
    int m0 = blockIdx.y * BM, n0 = blockIdx.x * BN;
    int tid = threadIdx.x;
    int tx = tid & 15, ty = tid >> 4;
    int la_r = tid >> 2;
    int la_k = (tid & 3) * 4;
    int lb_k = tid >> 4;
    int lb_n = (tid & 15) * 4;
    float acc[4][4];
#pragma unroll
    for (int i = 0; i < 4; i++)
#pragma unroll
        for (int jj = 0; jj < 4; jj++) acc[i][jj] = 0.0f;
    for (int kb = 0; kb < K; kb += BK) {
        int m = m0 + la_r;
#pragma unroll
        for (int u = 0; u < 4; u++) {
            int k = kb + la_k + u;
            As[la_k + u][la_r] = (k < K && m < M) ? A[(size_t)m * K + k] : 0.0f;
        }
        int kB = kb + lb_k;
#pragma unroll
        for (int u = 0; u < 4; u++) {
            int n = n0 + lb_n + u;
            Bs[lb_k][lb_n + u] = (kB < K && n < Nc) ? B[(size_t)kB * ldb + n] : 0.0f;
        }
        __syncthreads();
#pragma unroll
        for (int k = 0; k < BK; k++) {
            float4 a = *(const float4*)&As[k][ty * 4];
            float4 b = *(const float4*)&Bs[k][tx * 4];
            acc[0][0] += a.x * b.x; acc[0][1] += a.x * b.y; acc[0][2] += a.x * b.z; acc[0][3] += a.x * b.w;
            acc[1][0] += a.y * b.x; acc[1][1] += a.y * b.y; acc[1][2] += a.y * b.z; acc[1][3] += a.y * b.w;
            acc[2][0] += a.z * b.x; acc[2][1] += a.z * b.y; acc[2][2] += a.z * b.z; acc[2][3] += a.z * b.w;
            acc[3][0] += a.w * b.x; acc[3][1] += a.w * b.y; acc[3][2] += a.w * b.z; acc[3][3] += a.w * b.w;
        }
        __syncthreads();
    }
#pragma unroll
    for (int i = 0; i < 4; i++) {
        int m = m0 + ty * 4 + i;
        if (m >= M) continue;
#pragma unroll
        for (int jj = 0; jj < 4; jj++) {
            int n = n0 + tx * 4 + jj;
            if (n < Nc) C[(size_t)m * Nc + n] = acc[i][jj];
        }
    }
}

// ---------------- edge aggregation (deterministic, gather-side) ----------------
#define MAXD 512
__global__ void __launch_bounds__(128) k_edge() {
    int i = blockIdx.x;
    int f = threadIdx.x;
    int s0 = g_start[i], s1 = g_start[i + 1];
    int L = s1 - s0;
    __shared__ int se[MAXD];
    __shared__ int ord[MAXD];
    bool srt = (L <= MAXD);
    if (srt && L > 0) {
        for (int a = f; a < L; a += 128) se[a] = g_eo[s0 + a];
        __syncthreads();
        for (int a = f; a < L; a += 128) {
            int my = se[a];
            int r = 0;
            for (int b = 0; b < L; b++) r += (se[b] < my);
            ord[r] = a;
        }
        __syncthreads();
    }
    float aq = 0.0f, m0 = 0.0f, m1 = 0.0f, m2 = 0.0f;
    for (int a = 0; a < L; a++) {
        int slot = s0 + (srt ? ord[a] : a);
        int j = g_js[slot];
        float d0 = g_dir[3 * slot + 0];
        float d1 = g_dir[3 * slot + 1];
        float d2 = g_dir[3 * slot + 2];
        size_t fbx = (size_t)slot * 384;
        float fq = g_filt[fbx + f];
        float fR = g_filt[fbx + 128 + f];
        float fM = g_filt[fbx + 256 + f];
        size_t xb = (size_t)j * 384;
        float xq = g_x[xb + f];
        float xR = g_x[xb + 128 + f];
        float xM = g_x[xb + 256 + f];
        float mj0 = g_muA[xb + f];
        float mj1 = g_muA[xb + 128 + f];
        float mj2 = g_muA[xb + 256 + f];
        aq += fq * xq;
        float tR = fR * xR, tM = fM * xM;
        m0 += tR * d0 + tM * mj0;
        m1 += tR * d1 + tM * mj1;
        m2 += tR * d2 + tM * mj2;
    }
    size_t mb_ = (size_t)i * 384;
    g_q[(size_t)i * 128 + f] += aq;
    float b0 = g_muA[mb_ + f] + m0;
    float b1 = g_muA[mb_ + 128 + f] + m1;
    float b2 = g_muA[mb_ + 256 + f] + m2;
    g_muB[mb_ + f] = b0;
    g_muB[mb_ + 128 + f] = b1;
    g_muB[mb_ + 256 + f] = b2;
    size_t hb = (size_t)i * 768;
    __nv_bfloat16 h0 = __float2bfloat16(b0);
    __nv_bfloat16 h1 = __float2bfloat16(b1);
    __nv_bfloat16 h2 = __float2bfloat16(b2);
    g_muBhl[hb + f] = h0;
    g_muBhl[hb + 128 + f] = __float2bfloat16(b0 - __bfloat162float(h0));
    g_muBhl[hb + 256 + f] = h1;
    g_muBhl[hb + 384 + f] = __float2bfloat16(b1 - __bfloat162float(h1));
    g_muBhl[hb + 512 + f] = h2;
    g_muBhl[hb + 640 + f] = __float2bfloat16(b2 - __bfloat162float(h2));
}

// ---------------- mixing elementwise ----------------
__global__ void k_ctx() {
    int n = blockIdx.x;
    int f = threadIdx.x;
    size_t mmb = (size_t)n * 768;
    float v0 = g_mm[mmb + f];
    float v1 = g_mm[mmb + 256 + f];
    float v2 = g_mm[mmb + 512 + f];
    float w0 = g_mm[mmb + 128 + f];
    float w1 = g_mm[mmb + 384 + f];
    float w2 = g_mm[mmb + 640 + f];
    float vn = sqrtf(v0 * v0 + v1 * v1 + v2 * v2 + 1e-8f);
    float s = v0 * w0 + v1 * w1 + v2 * w2;
    float qv = g_q[(size_t)n * 128 + f];
    size_t cb = (size_t)n * 512;
    __nv_bfloat16 qh = __float2bfloat16(qv);
    __nv_bfloat16 vh = __float2bfloat16(vn);
    g_ctxhl[cb + f] = qh;
    g_ctxhl[cb + 128 + f] = vh;
    g_ctxhl[cb + 256 + f] = __float2bfloat16(qv - __bfloat162float(qh));
    g_ctxhl[cb + 384 + f] = __float2bfloat16(vn - __bfloat162float(vh));
    g_s[(size_t)n * 128 + f] = s;
}

__global__ void k_update() {
    int n = blockIdx.x;
    int f = threadIdx.x;
    size_t xb = (size_t)n * 384;
    float dq  = g_x[xb + f];
    float dmc = g_x[xb + 128 + f];
    float dqm = g_x[xb + 256 + f];
    float qn = g_q[(size_t)n * 128 + f] + dq + dqm * g_s[(size_t)n * 128 + f];
    g_q[(size_t)n * 128 + f] = qn;
    __nv_bfloat16 qh = __float2bfloat16(qn);
    g_qhl[(size_t)n * 256 + f] = qh;
    g_qhl[(size_t)n * 256 + 128 + f] = __float2bfloat16(qn - __bfloat162float(qh));
    size_t mmb = (size_t)n * 768;
    g_muA[xb + f]       = g_muB[xb + f]       + dmc * g_mm[mmb + 128 + f];
    g_muA[xb + 128 + f] = g_muB[xb + 128 + f] + dmc * g_mm[mmb + 384 + f];
    g_muA[xb + 256 + f] = g_muB[xb + 256 + f] + dmc * g_mm[mmb + 640 + f];
}

// ---------------- launcher ----------------
extern "C" void kernel_launch(void* const* d_in, const int* in_sizes, int n_in,
                              void* d_out, int out_size) {
    const int*   z     = (const int*)d_in[0];
    const float* pos   = (const float*)d_in[1];
    const int*   idx_i = (const int*)d_in[2];
    const int*   idx_j = (const int*)d_in[3];
    const float* emb   = (const float*)d_in[4];
    const float* fW    = (const float*)d_in[5];
    const float* fb    = (const float*)d_in[6];
    const float* iW1   = (const float*)d_in[7];
    const float* ib1   = (const float*)d_in[8];
    const float* iW2   = (const float*)d_in[9];
    const float* ib2   = (const float*)d_in[10];
    const float* mWmix = (const float*)d_in[11];
    const float* mW1   = (const float*)d_in[12];
    const float* mb1   = (const float*)d_in[13];
    const float* mW2   = (const float*)d_in[14];
    const float* mb2   = (const float*)d_in[15];
    float* out = (float*)d_out;

    void *p_cnt, *p_muA, *p_q, *p_x, *p_mm, *p_phiS, *p_fWX, *p_filt;
    void *p_qhl, *p_hhl, *p_ctxhl, *p_muBhl, *p_WT1, *p_WT2, *p_WTmix, *p_WTm1, *p_WTm2;
    cudaGetSymbolAddress(&p_cnt, g_cnt);
    cudaGetSymbolAddress(&p_muA, g_muA);
    cudaGetSymbolAddress(&p_q, g_q);
    cudaGetSymbolAddress(&p_x, g_x);
    cudaGetSymbolAddress(&p_mm, g_mm);
    cudaGetSymbolAddress(&p_phiS, g_phiS);
    cudaGetSymbolAddress(&p_fWX, g_fWX);
    cudaGetSymbolAddress(&p_filt, g_filt);
    cudaGetSymbolAddress(&p_qhl, g_qhl);
    cudaGetSymbolAddress(&p_hhl, g_hhl);
    cudaGetSymbolAddress(&p_ctxhl, g_ctxhl);
    cudaGetSymbolAddress(&p_muBhl, g_muBhl);
    cudaGetSymbolAddress(&p_WT1, g_WT1);
    cudaGetSymbolAddress(&p_WT2, g_WT2);
    cudaGetSymbolAddress(&p_WTmix, g_WTmix);
    cudaGetSymbolAddress(&p_WTm1, g_WTm1);
    cudaGetSymbolAddress(&p_WTm2, g_WTm2);

    cudaMemsetAsync(p_cnt, 0, NA * sizeof(int));
    cudaMemsetAsync(p_muA, 0, (size_t)NA * 384 * sizeof(float));

    k_fwx<<<(1152 + 127) / 128, 128>>>(fW, fb);
    k_count<<<(NE + 255) / 256, 256>>>(idx_i);
    k_scan<<<1, 1024>>>();
    k_build<<<(NE + 127) / 128, 128>>>(pos, idx_i, idx_j);
    k_init_q<<<NA, 128>>>(z, emb);
    k_wsplit<<<dim3((128 * 128 + 255) / 256, 3), 256>>>(iW1, (__nv_bfloat16*)p_WT1, 128, 128);
    k_wsplit<<<dim3((128 * 384 + 255) / 256, 3), 256>>>(iW2, (__nv_bfloat16*)p_WT2, 128, 384);
    k_wsplit<<<dim3((128 * 256 + 255) / 256, 3), 256>>>(mWmix, (__nv_bfloat16*)p_WTmix, 128, 256);
    k_wsplit<<<dim3((256 * 128 + 255) / 256, 3), 256>>>(mW1, (__nv_bfloat16*)p_WTm1, 256, 128);
    k_wsplit<<<dim3((128 * 384 + 255) / 256, 3), 256>>>(mW2, (__nv_bfloat16*)p_WTm2, 128, 384);

    const __nv_bfloat16* qhl = (const __nv_bfloat16*)p_qhl;
    const __nv_bfloat16* hhl = (const __nv_bfloat16*)p_hhl;
    const __nv_bfloat16* ctxhl = (const __nv_bfloat16*)p_ctxhl;
    const __nv_bfloat16* muBhl = (const __nv_bfloat16*)p_muBhl;
    const float* fphiS = (const float*)p_phiS;
    const float* ffWX = (const float*)p_fWX;

    int ga = (NA + 127) / 128;      // 196
    int gm = (NA * 3 + 127) / 128;  // 586
    int gy_e = (NE + BM - 1) / BM;

    for (int t = 0; t < 3; t++) {
        // H1 = silu(q @ iW1 + ib1) -> hhl
        k_wgemm<<<dim3(ga, 2), 256, SMEM_WG>>>(
            qhl, (const __nv_bfloat16*)p_WT1 + (size_t)t * 128 * 256,
            ib1 + t * 128, nullptr, (__nv_bfloat16*)p_hhl, NA, 128, 128, 1);
        // X = H1 @ iW2 + ib2 -> g_x (fp32)
        k_wgemm<<<dim3(ga, 6), 256, SMEM_WG>>>(
            hhl, (const __nv_bfloat16*)p_WT2 + (size_t)t * 384 * 256,
            ib2 + t * 384, (float*)p_x, nullptr, NA, 128, 384, 0);
        // FILT = phiS @ fWX[:, t*384:(t+1)*384]
        k_gemm<<<dim3(6, gy_e), 256>>>(fphiS, ffWX + t * 384, (float*)p_filt, NE, 21, 384, 1152);
        // edge aggregation
        k_edge<<<NA, 128>>>();
        // MUMIX = muB @ mWmix -> g_mm (fp32)
        k_wgemm<<<dim3(gm, 4), 256, SMEM_WG>>>(
            muBhl, (const __nv_bfloat16*)p_WTmix + (size_t)t * 256 * 256,
            nullptr, (float*)p_mm, nullptr, NA * 3, 128, 256, 0);
        k_ctx<<<NA, 128>>>();
        // H2 = silu(ctx @ mW1 + mb1) -> hhl   (K=256)
        k_wgemm<<<dim3(ga, 2), 256, SMEM_WG>>>(
            ctxhl, (const __nv_bfloat16*)p_WTm1 + (size_t)t * 128 * 512,
            mb1 + t * 128, nullptr, (__nv_bfloat16*)p_hhl, NA, 256, 128, 1);
        // X2 = H2 @ mW2 + mb2 -> g_x (fp32)
        k_wgemm<<<dim3(ga, 6), 256, SMEM_WG>>>(
            hhl, (const __nv_bfloat16*)p_WTm2 + (size_t)t * 384 * 256,
            mb2 + t * 384, (float*)p_x, nullptr, NA, 128, 384, 0);
        k_update<<<NA, 128>>>();
    }

    cudaMemcpyAsync(out, p_q, (size_t)NA * 128 * sizeof(float), cudaMemcpyDeviceToDevice);
    cudaMemcpyAsync(out + (size_t)NA * 128, p_muA, (size_t)NA * 384 * sizeof(float),
                    cudaMemcpyDeviceToDevice);
}

// round 10
// speedup vs baseline: 1.5265x; 1.1287x over previous
#include <cuda_runtime.h>
#include <cuda_bf16.h>
#include <mma.h>
#include <math.h>
#include <stdint.h>

using namespace nvcuda;

#define NA 25000
#define NE 200000

// ---------------- static scratch ----------------
__device__ float g_dir[(size_t)NE * 3];
__device__ int   g_js[NE];
__device__ int   g_eo[NE];
__device__ int   g_cnt[NA];
__device__ int   g_start[NA + 1];
__device__ int   g_cursor[NA];
__device__ float g_q[(size_t)NA * 128];
__device__ float g_x[(size_t)NA * 384];
__device__ float g_muA[(size_t)NA * 384];
__device__ float g_muB[(size_t)NA * 384];
__device__ float g_mm[(size_t)NA * 768];
__device__ float g_s[(size_t)NA * 128];
__device__ float g_filt[(size_t)NE * 384];
// bf16 hi/lo activation buffers ([M, 2K]: hi cols [0,K), lo cols [K,2K))
__device__ __nv_bfloat16 g_qhl[(size_t)NA * 256];
__device__ __nv_bfloat16 g_hhl[(size_t)NA * 256];
__device__ __nv_bfloat16 g_ctxhl[(size_t)NA * 512];
__device__ __nv_bfloat16 g_muBhl[(size_t)NA * 768];
__device__ __nv_bfloat16 g_phiHL[(size_t)NE * 64];   // [E, 2*32] hi|lo, K padded 21->32
__device__ __nv_bfloat16 g_fWXhl[1152 * 64];         // [1152, 2*32] hi|lo (fb folded row 20)
// bf16 transposed+split weights ([N, 2K] per t)
__device__ __nv_bfloat16 g_WT1[3 * 128 * 256];
__device__ __nv_bfloat16 g_WT2[3 * 384 * 256];
__device__ __nv_bfloat16 g_WTmix[3 * 256 * 256];
__device__ __nv_bfloat16 g_WTm1[3 * 128 * 512];
__device__ __nv_bfloat16 g_WTm2[3 * 384 * 256];

// ---------------- helpers ----------------
__device__ __forceinline__ uint32_t smem_u32(const void* p) {
    uint32_t a;
    asm("{ .reg .u64 t; cvta.to.shared.u64 t, %1; cvt.u32.u64 %0, t; }" : "=r"(a) : "l"(p));
    return a;
}
__device__ __forceinline__ void cp16(void* dst, const void* src, int sz) {
    uint32_t d = smem_u32(dst);
    asm volatile("cp.async.cg.shared.global [%0], [%1], 16, %2;\n" :: "r"(d), "l"(src), "r"(sz));
}

// ---------------- pipelined wmma GEMM: C = act(A @ W^T + bias) ----------------
// A: [M, 2K] bf16 hi|lo.  W: [N, 2K] bf16 hi|lo (K-major).
// 3-term bf16x3: Ahi*Whi + Alo*Whi + Ahi*Wlo, fp32 accumulate.
// CTA tile 128x128, 8 warps (4m x 2n), warp tile 32x64, BK=32, 2-stage cp.async.
#define TPAD 40
#define TSTG (128 * TPAD)  // elements per tile stage
__global__ void __launch_bounds__(256) k_wgemm(
    const __nv_bfloat16* __restrict__ A, const __nv_bfloat16* __restrict__ W,
    const float* __restrict__ bias, float* __restrict__ Cf,
    __nv_bfloat16* __restrict__ Chl, int M, int K, int N, int act) {
    extern __shared__ char smem[];
    __nv_bfloat16* As = (__nv_bfloat16*)smem;              // [2][128*TPAD]
    __nv_bfloat16* Bs = As + 2 * TSTG;                     // [2][128*TPAD]
    int tid = threadIdx.x;
    int wid = tid >> 5;
    int m0 = blockIdx.x * 128, n0 = blockIdx.y * 128;
    int lda = 2 * K;
    int wm = wid & 3, wn = wid >> 2;

    wmma::fragment<wmma::accumulator, 16, 16, 16, float> acc[2][4];
#pragma unroll
    for (int i = 0; i < 2; i++)
#pragma unroll
        for (int j = 0; j < 4; j++) wmma::fill_fragment(acc[i][j], 0.0f);

    int kchunks = K >> 5;
    int ksteps = 3 * kchunks;
    int r_ld = tid >> 2, c8 = (tid & 3) * 8;  // 64 rows per 256t pass, 4x16B cols

    // stage loader: A/B tiles [128 x 32] via cp.async, 4 chunks/thread
    auto load_stage = [&](int step, int buf) {
        int ph = step / kchunks, kb = step % kchunks;
        int ka = (ph == 1 ? K : 0) + kb * 32;
        int kw = (ph == 2 ? K : 0) + kb * 32;
        __nv_bfloat16* a_dst = As + buf * TSTG;
        __nv_bfloat16* b_dst = Bs + buf * TSTG;
#pragma unroll
        for (int u = 0; u < 2; u++) {
            int r = r_ld + u * 64;
            int m = m0 + r;
            int mc = (m < M) ? m : (M - 1);
            cp16(a_dst + r * TPAD + c8, A + (size_t)mc * lda + ka + c8, (m < M) ? 16 : 0);
            cp16(b_dst + r * TPAD + c8, W + (size_t)(n0 + r) * lda + kw + c8, 16);
        }
        asm volatile("cp.async.commit_group;\n" ::: "memory");
    };

    load_stage(0, 0);
    for (int step = 0; step < ksteps; step++) {
        int buf = step & 1;
        if (step + 1 < ksteps) {
            load_stage(step + 1, buf ^ 1);
            asm volatile("cp.async.wait_group 1;\n" ::: "memory");
        } else {
            asm volatile("cp.async.wait_group 0;\n" ::: "memory");
        }
        __syncthreads();
        const __nv_bfloat16* Asb = As + buf * TSTG;
        const __nv_bfloat16* Bsb = Bs + buf * TSTG;
#pragma unroll
        for (int kk = 0; kk < 32; kk += 16) {
            wmma::fragment<wmma::matrix_a, 16, 16, 16, __nv_bfloat16, wmma::row_major> af[2];
            wmma::fragment<wmma::matrix_b, 16, 16, 16, __nv_bfloat16, wmma::col_major> bf[4];
#pragma unroll
            for (int i = 0; i < 2; i++)
                wmma::load_matrix_sync(af[i], Asb + (wm * 32 + i * 16) * TPAD + kk, TPAD);
#pragma unroll
            for (int j = 0; j < 4; j++)
                wmma::load_matrix_sync(bf[j], Bsb + (wn * 64 + j * 16) * TPAD + kk, TPAD);
#pragma unroll
            for (int i = 0; i < 2; i++)
#pragma unroll
                for (int j = 0; j < 4; j++)
                    wmma::mma_sync(acc[i][j], af[i], bf[j], acc[i][j]);
        }
        __syncthreads();
    }

    // epilogue in two 64-col halves through 32KB smem staging
    float* stg = (float*)smem;
#pragma unroll
    for (int h = 0; h < 2; h++) {
        if (wn == h) {
#pragma unroll
            for (int i = 0; i < 2; i++)
#pragma unroll
                for (int j = 0; j < 4; j++)
                    wmma::store_matrix_sync(stg + (wm * 32 + i * 16) * 64 + j * 16,
                                            acc[i][j], 64, wmma::mem_row_major);
        }
        __syncthreads();
#pragma unroll
        for (int u = 0; u < 8; u++) {
            int idx = tid + u * 256;
            int r = idx >> 4, c4 = (idx & 15) * 4;
            int m = m0 + r;
            if (m < M) {
                float4 v = *(float4*)&stg[r * 64 + c4];
                int n = n0 + h * 64 + c4;
                if (bias) {
                    v.x += bias[n + 0]; v.y += bias[n + 1];
                    v.z += bias[n + 2]; v.w += bias[n + 3];
                }
                if (act) {
                    v.x = v.x / (1.0f + __expf(-v.x));
                    v.y = v.y / (1.0f + __expf(-v.y));
                    v.z = v.z / (1.0f + __expf(-v.z));
                    v.w = v.w / (1.0f + __expf(-v.w));
                }
                if (Cf) {
                    *(float4*)(Cf + (size_t)m * N + n) = v;
                } else {
                    __nv_bfloat16 h0 = __float2bfloat16(v.x), h1 = __float2bfloat16(v.y);
                    __nv_bfloat16 h2 = __float2bfloat16(v.z), h3 = __float2bfloat16(v.w);
                    __nv_bfloat16 l0 = __float2bfloat16(v.x - __bfloat162float(h0));
                    __nv_bfloat16 l1 = __float2bfloat16(v.y - __bfloat162float(h1));
                    __nv_bfloat16 l2 = __float2bfloat16(v.z - __bfloat162float(h2));
                    __nv_bfloat16 l3 = __float2bfloat16(v.w - __bfloat162float(h3));
                    __nv_bfloat16* ph = Chl + (size_t)m * 2 * N + n;
                    *(__nv_bfloat162*)(ph + 0) = __nv_bfloat162(h0, h1);
                    *(__nv_bfloat162*)(ph + 2) = __nv_bfloat162(h2, h3);
                    __nv_bfloat16* pl = Chl + (size_t)m * 2 * N + N + n;
                    *(__nv_bfloat162*)(pl + 0) = __nv_bfloat162(l0, l1);
                    *(__nv_bfloat162*)(pl + 2) = __nv_bfloat162(l2, l3);
                }
            }
        }
        __syncthreads();
    }
}
#define SMEM_WG (4 * TSTG * 2)  // 40960 bytes

// ---------------- prep kernels ----------------
__global__ void k_fwx(const float* __restrict__ fW, const float* __restrict__ fb) {
    int n = blockIdx.x * blockDim.x + threadIdx.x;
    if (n >= 1152) return;
    for (int k = 0; k < 32; k++) {
        float v = 0.0f;
        if (k < 20) v = fW[k * 1152 + n];
        else if (k == 20) v = fb[n];
        __nv_bfloat16 hi = __float2bfloat16(v);
        g_fWXhl[n * 64 + k] = hi;
        g_fWXhl[n * 64 + 32 + k] = __float2bfloat16(v - __bfloat162float(hi));
    }
}

// transpose [K,N] fp32 -> [N,2K] bf16 hi|lo, for 3 t's
__global__ void k_wsplit(const float* __restrict__ src, __nv_bfloat16* __restrict__ dst,
                         int K, int N) {
    int t = blockIdx.y;
    int id = blockIdx.x * 256 + threadIdx.x;
    if (id >= K * N) return;
    int k = id / N, n = id % N;
    float v = src[(size_t)t * K * N + (size_t)k * N + n];
    __nv_bfloat16 hi = __float2bfloat16(v);
    float lo = v - __bfloat162float(hi);
    size_t base = (size_t)t * N * 2 * K + (size_t)n * 2 * K;
    dst[base + k] = hi;
    dst[base + K + k] = __float2bfloat16(lo);
}

__global__ void k_count(const int* __restrict__ idx_i) {
    int e = blockIdx.x * blockDim.x + threadIdx.x;
    if (e < NE) atomicAdd(&g_cnt[idx_i[e]], 1);
}

__global__ void k_scan() {
    __shared__ int sm[1024];
    __shared__ int carry_s;
    int tid = threadIdx.x;
    if (tid == 0) carry_s = 0;
    __syncthreads();
    for (int base = 0; base < NA; base += 1024) {
        int idx = base + tid;
        int v = (idx < NA) ? g_cnt[idx] : 0;
        sm[tid] = v;
        __syncthreads();
        for (int off = 1; off < 1024; off <<= 1) {
            int t = (tid >= off) ? sm[tid - off] : 0;
            __syncthreads();
            sm[tid] += t;
            __syncthreads();
        }
        int out = carry_s + sm[tid] - v;
        if (idx < NA) { g_start[idx] = out; g_cursor[idx] = out; }
        int tot = sm[1023];
        __syncthreads();
        if (tid == 0) carry_s += tot;
        __syncthreads();
    }
    if (tid == 0) g_start[NA] = carry_s;
}

__global__ void k_build(const float* __restrict__ pos,
                        const int* __restrict__ idx_i,
                        const int* __restrict__ idx_j) {
    int e = blockIdx.x * blockDim.x + threadIdx.x;
    if (e >= NE) return;
    int i = idx_i[e], j = idx_j[e];
    float r0 = pos[3 * j + 0] - pos[3 * i + 0];
    float r1 = pos[3 * j + 1] - pos[3 * i + 1];
    float r2 = pos[3 * j + 2] - pos[3 * i + 2];
    r0 = (fabsf(r0) < 1e-6f) ? 1e-6f : r0;
    r1 = (fabsf(r1) < 1e-6f) ? 1e-6f : r1;
    r2 = (fabsf(r2) < 1e-6f) ? 1e-6f : r2;
    float d = sqrtf(r0 * r0 + r1 * r1 + r2 * r2);
    float inv = 1.0f / d;
    float fc = (d < 5.0f) ? 0.5f * (cosf(0.628318530717959f * d) + 1.0f) : 0.0f;
    int slot = atomicAdd(&g_cursor[i], 1);
    g_js[slot] = j;
    g_eo[slot] = e;
    g_dir[3 * slot + 0] = r0 * inv;
    g_dir[3 * slot + 1] = r1 * inv;
    g_dir[3 * slot + 2] = r2 * inv;
    const float step = 5.0f / 19.0f;
    const float coeff = -7.22f;
    size_t pb = (size_t)slot * 64;
    for (int k = 0; k < 32; k++) {
        float v = 0.0f;
        if (k < 20) {
            float df = d - (float)k * step;
            v = expf(coeff * df * df) * fc;
        } else if (k == 20) {
            v = fc;
        }
        __nv_bfloat16 hi = __float2bfloat16(v);
        g_phiHL[pb + k] = hi;
        g_phiHL[pb + 32 + k] = __float2bfloat16(v - __bfloat162float(hi));
    }
}

__global__ void k_init_q(const int* __restrict__ z, const float* __restrict__ emb) {
    int n = blockIdx.x;
    int f = threadIdx.x;
    float v = emb[(size_t)z[n] * 128 + f];
    g_q[(size_t)n * 128 + f] = v;
    __nv_bfloat16 hi = __float2bfloat16(v);
    g_qhl[(size_t)n * 256 + f] = hi;
    g_qhl[(size_t)n * 256 + 128 + f] = __float2bfloat16(v - __bfloat162float(hi));
}

// ---------------- edge aggregation (deterministic, gather-side) ----------------
#define MAXD 512
__global__ void __launch_bounds__(128) k_edge() {
    int i = blockIdx.x;
    int f = threadIdx.x;
    int s0 = g_start[i], s1 = g_start[i + 1];
    int L = s1 - s0;
    __shared__ int se[MAXD];
    __shared__ int ord[MAXD];
    bool srt = (L <= MAXD);
    if (srt && L > 0) {
        for (int a = f; a < L; a += 128) se[a] = g_eo[s0 + a];
        __syncthreads();
        for (int a = f; a < L; a += 128) {
            int my = se[a];
            int r = 0;
            for (int b = 0; b < L; b++) r += (se[b] < my);
            ord[r] = a;
        }
        __syncthreads();
    }
    float aq = 0.0f, m0 = 0.0f, m1 = 0.0f, m2 = 0.0f;
    for (int a = 0; a < L; a++) {
        int slot = s0 + (srt ? ord[a] : a);
        int j = g_js[slot];
        float d0 = g_dir[3 * slot + 0];
        float d1 = g_dir[3 * slot + 1];
        float d2 = g_dir[3 * slot + 2];
        size_t fbx = (size_t)slot * 384;
        float fq = g_filt[fbx + f];
        float fR = g_filt[fbx + 128 + f];
        float fM = g_filt[fbx + 256 + f];
        size_t xb = (size_t)j * 384;
        float xq = g_x[xb + f];
        float xR = g_x[xb + 128 + f];
        float xM = g_x[xb + 256 + f];
        float mj0 = g_muA[xb + f];
        float mj1 = g_muA[xb + 128 + f];
        float mj2 = g_muA[xb + 256 + f];
        aq += fq * xq;
        float tR = fR * xR, tM = fM * xM;
        m0 += tR * d0 + tM * mj0;
        m1 += tR * d1 + tM * mj1;
        m2 += tR * d2 + tM * mj2;
    }
    size_t mb_ = (size_t)i * 384;
    g_q[(size_t)i * 128 + f] += aq;
    float b0 = g_muA[mb_ + f] + m0;
    float b1 = g_muA[mb_ + 128 + f] + m1;
    float b2 = g_muA[mb_ + 256 + f] + m2;
    g_muB[mb_ + f] = b0;
    g_muB[mb_ + 128 + f] = b1;
    g_muB[mb_ + 256 + f] = b2;
    size_t hb = (size_t)i * 768;
    __nv_bfloat16 h0 = __float2bfloat16(b0);
    __nv_bfloat16 h1 = __float2bfloat16(b1);
    __nv_bfloat16 h2 = __float2bfloat16(b2);
    g_muBhl[hb + f] = h0;
    g_muBhl[hb + 128 + f] = __float2bfloat16(b0 - __bfloat162float(h0));
    g_muBhl[hb + 256 + f] = h1;
    g_muBhl[hb + 384 + f] = __float2bfloat16(b1 - __bfloat162float(h1));
    g_muBhl[hb + 512 + f] = h2;
    g_muBhl[hb + 640 + f] = __float2bfloat16(b2 - __bfloat162float(h2));
}

// ---------------- mixing elementwise ----------------
__global__ void k_ctx() {
    int n = blockIdx.x;
    int f = threadIdx.x;
    size_t mmb = (size_t)n * 768;
    float v0 = g_mm[mmb + f];
    float v1 = g_mm[mmb + 256 + f];
    float v2 = g_mm[mmb + 512 + f];
    float w0 = g_mm[mmb + 128 + f];
    float w1 = g_mm[mmb + 384 + f];
    float w2 = g_mm[mmb + 640 + f];
    float vn = sqrtf(v0 * v0 + v1 * v1 + v2 * v2 + 1e-8f);
    float s = v0 * w0 + v1 * w1 + v2 * w2;
    float qv = g_q[(size_t)n * 128 + f];
    size_t cb = (size_t)n * 512;
    __nv_bfloat16 qh = __float2bfloat16(qv);
    __nv_bfloat16 vh = __float2bfloat16(vn);
    g_ctxhl[cb + f] = qh;
    g_ctxhl[cb + 128 + f] = vh;
    g_ctxhl[cb + 256 + f] = __float2bfloat16(qv - __bfloat162float(qh));
    g_ctxhl[cb + 384 + f] = __float2bfloat16(vn - __bfloat162float(vh));
    g_s[(size_t)n * 128 + f] = s;
}

__global__ void k_update() {
    int n = blockIdx.x;
    int f = threadIdx.x;
    size_t xb = (size_t)n * 384;
    float dq  = g_x[xb + f];
    float dmc = g_x[xb + 128 + f];
    float dqm = g_x[xb + 256 + f];
    float qn = g_q[(size_t)n * 128 + f] + dq + dqm * g_s[(size_t)n * 128 + f];
    g_q[(size_t)n * 128 + f] = qn;
    __nv_bfloat16 qh = __float2bfloat16(qn);
    g_qhl[(size_t)n * 256 + f] = qh;
    g_qhl[(size_t)n * 256 + 128 + f] = __float2bfloat16(qn - __bfloat162float(qh));
    size_t mmb = (size_t)n * 768;
    g_muA[xb + f]       = g_muB[xb + f]       + dmc * g_mm[mmb + 128 + f];
    g_muA[xb + 128 + f] = g_muB[xb + 128 + f] + dmc * g_mm[mmb + 384 + f];
    g_muA[xb + 256 + f] = g_muB[xb + 256 + f] + dmc * g_mm[mmb + 640 + f];
}

// ---------------- launcher ----------------
extern "C" void kernel_launch(void* const* d_in, const int* in_sizes, int n_in,
                              void* d_out, int out_size) {
    const int*   z     = (const int*)d_in[0];
    const float* pos   = (const float*)d_in[1];
    const int*   idx_i = (const int*)d_in[2];
    const int*   idx_j = (const int*)d_in[3];
    const float* emb   = (const float*)d_in[4];
    const float* fW    = (const float*)d_in[5];
    const float* fb    = (const float*)d_in[6];
    const float* iW1   = (const float*)d_in[7];
    const float* ib1   = (const float*)d_in[8];
    const float* iW2   = (const float*)d_in[9];
    const float* ib2   = (const float*)d_in[10];
    const float* mWmix = (const float*)d_in[11];
    const float* mW1   = (const float*)d_in[12];
    const float* mb1   = (const float*)d_in[13];
    const float* mW2   = (const float*)d_in[14];
    const float* mb2   = (const float*)d_in[15];
    float* out = (float*)d_out;

    void *p_cnt, *p_muA, *p_q, *p_x, *p_mm, *p_filt;
    void *p_qhl, *p_hhl, *p_ctxhl, *p_muBhl, *p_phiHL, *p_fWXhl;
    void *p_WT1, *p_WT2, *p_WTmix, *p_WTm1, *p_WTm2;
    cudaGetSymbolAddress(&p_cnt, g_cnt);
    cudaGetSymbolAddress(&p_muA, g_muA);
    cudaGetSymbolAddress(&p_q, g_q);
    cudaGetSymbolAddress(&p_x, g_x);
    cudaGetSymbolAddress(&p_mm, g_mm);
    cudaGetSymbolAddress(&p_filt, g_filt);
    cudaGetSymbolAddress(&p_qhl, g_qhl);
    cudaGetSymbolAddress(&p_hhl, g_hhl);
    cudaGetSymbolAddress(&p_ctxhl, g_ctxhl);
    cudaGetSymbolAddress(&p_muBhl, g_muBhl);
    cudaGetSymbolAddress(&p_phiHL, g_phiHL);
    cudaGetSymbolAddress(&p_fWXhl, g_fWXhl);
    cudaGetSymbolAddress(&p_WT1, g_WT1);
    cudaGetSymbolAddress(&p_WT2, g_WT2);
    cudaGetSymbolAddress(&p_WTmix, g_WTmix);
    cudaGetSymbolAddress(&p_WTm1, g_WTm1);
    cudaGetSymbolAddress(&p_WTm2, g_WTm2);

    const __nv_bfloat16* qhl = (const __nv_bfloat16*)p_qhl;
    const __nv_bfloat16* hhl = (const __nv_bfloat16*)p_hhl;
    const __nv_bfloat16* ctxhl = (const __nv_bfloat16*)p_ctxhl;
    const __nv_bfloat16* muBhl = (const __nv_bfloat16*)p_muBhl;
    const __nv_bfloat16* phiHL = (const __nv_bfloat16*)p_phiHL;

    int ga = (NA + 127) / 128;       // 196
    int gm = (NA * 3 + 127) / 128;   // 586
    int ge = (NE + 127) / 128;       // 1563

    // ---- prep, ordered so the first flagship GEMM is launch #6 (ncu -s 5 -c 1) ----
    cudaMemsetAsync(p_cnt, 0, NA * sizeof(int));                       // 1
    cudaMemsetAsync(p_muA, 0, (size_t)NA * 384 * sizeof(float));       // 2
    k_init_q<<<NA, 128>>>(z, emb);                                     // 3
    k_wsplit<<<dim3((128 * 128 + 255) / 256, 3), 256>>>(iW1, (__nv_bfloat16*)p_WT1, 128, 128);   // 4
    k_wsplit<<<dim3((128 * 384 + 255) / 256, 3), 256>>>(iW2, (__nv_bfloat16*)p_WT2, 128, 384);   // 5
    // H1(t=0): launch #6 -> profiled
    k_wgemm<<<dim3(ga, 1), 256, SMEM_WG>>>(
        qhl, (const __nv_bfloat16*)p_WT1, ib1, nullptr, (__nv_bfloat16*)p_hhl, NA, 128, 128, 1);
    k_wsplit<<<dim3((128 * 256 + 255) / 256, 3), 256>>>(mWmix, (__nv_bfloat16*)p_WTmix, 128, 256);
    k_wsplit<<<dim3((256 * 128 + 255) / 256, 3), 256>>>(mW1, (__nv_bfloat16*)p_WTm1, 256, 128);
    k_wsplit<<<dim3((128 * 384 + 255) / 256, 3), 256>>>(mW2, (__nv_bfloat16*)p_WTm2, 128, 384);
    k_fwx<<<(1152 + 127) / 128, 128>>>(fW, fb);
    k_count<<<(NE + 255) / 256, 256>>>(idx_i);
    k_scan<<<1, 1024>>>();
    k_build<<<(NE + 127) / 128, 128>>>(pos, idx_i, idx_j);

    for (int t = 0; t < 3; t++) {
        if (t > 0) {
            // H1 = silu(q @ iW1 + ib1) -> hhl
            k_wgemm<<<dim3(ga, 1), 256, SMEM_WG>>>(
                qhl, (const __nv_bfloat16*)p_WT1 + (size_t)t * 128 * 256,
                ib1 + t * 128, nullptr, (__nv_bfloat16*)p_hhl, NA, 128, 128, 1);
        }
        // X = H1 @ iW2 + ib2 -> g_x (fp32)
        k_wgemm<<<dim3(ga, 3), 256, SMEM_WG>>>(
            hhl, (const __nv_bfloat16*)p_WT2 + (size_t)t * 384 * 256,
            ib2 + t * 384, (float*)p_x, nullptr, NA, 128, 384, 0);
        // FILT = phiHL @ fWXhl[t-slice]^T (K padded to 32, fcut/bias folded)
        k_wgemm<<<dim3(ge, 3), 256, SMEM_WG>>>(
            phiHL, (const __nv_bfloat16*)p_fWXhl + (size_t)t * 384 * 64,
            nullptr, (float*)p_filt, nullptr, NE, 32, 384, 0);
        // edge aggregation
        k_edge<<<NA, 128>>>();
        // MUMIX = muB @ mWmix -> g_mm (fp32)
        k_wgemm<<<dim3(gm, 2), 256, SMEM_WG>>>(
            muBhl, (const __nv_bfloat16*)p_WTmix + (size_t)t * 256 * 256,
            nullptr, (float*)p_mm, nullptr, NA * 3, 128, 256, 0);
        k_ctx<<<NA, 128>>>();
        // H2 = silu(ctx @ mW1 + mb1) -> hhl   (K=256)
        k_wgemm<<<dim3(ga, 1), 256, SMEM_WG>>>(
            ctxhl, (const __nv_bfloat16*)p_WTm1 + (size_t)t * 128 * 512,
            mb1 + t * 128, nullptr, (__nv_bfloat16*)p_hhl, NA, 256, 128, 1);
        // X2 = H2 @ mW2 + mb2 -> g_x (fp32)
        k_wgemm<<<dim3(ga, 3), 256, SMEM_WG>>>(
            hhl, (const __nv_bfloat16*)p_WTm2 + (size_t)t * 384 * 256,
            mb2 + t * 384, (float*)p_x, nullptr, NA, 128, 384, 0);
        k_update<<<NA, 128>>>();
    }

    cudaMemcpyAsync(out, p_q, (size_t)NA * 128 * sizeof(float), cudaMemcpyDeviceToDevice);
    cudaMemcpyAsync(out + (size_t)NA * 128, p_muA, (size_t)NA * 384 * sizeof(float),
                    cudaMemcpyDeviceToDevice);
}

// round 12
// speedup vs baseline: 1.5731x; 1.0305x over previous
#include <cuda_runtime.h>
#include <cuda_bf16.h>
#include <mma.h>
#include <math.h>
#include <stdint.h>

using namespace nvcuda;

#define NA 25000
#define NE 200000

// ---------------- static scratch ----------------
__device__ float g_dir[(size_t)NE * 3];
__device__ int   g_js[NE];
__device__ int   g_eo[NE];
__device__ int   g_cnt[NA];
__device__ int   g_start[NA + 1];
__device__ int   g_cursor[NA];
__device__ float g_q[(size_t)NA * 128];
__device__ float g_x[(size_t)NA * 384];
__device__ float g_muA[(size_t)NA * 384];
__device__ float g_muB[(size_t)NA * 384];
__device__ float g_mm[(size_t)NA * 768];
__device__ float g_s[(size_t)NA * 128];
__device__ float g_filt[(size_t)NE * 384];
// bf16 hi/lo activation buffers ([M, 2K]: hi cols [0,K), lo cols [K,2K))
__device__ __nv_bfloat16 g_qhl[(size_t)NA * 256];
__device__ __nv_bfloat16 g_hhl[(size_t)NA * 256];
__device__ __nv_bfloat16 g_ctxhl[(size_t)NA * 512];
__device__ __nv_bfloat16 g_muBhl[(size_t)NA * 768];
// FILT operands, packed 3-term-in-K: A'=[phi_hi(21)|phi_lo(21)|phi_hi(21)|0] K=64
__device__ __nv_bfloat16 g_phiHL[(size_t)NE * 64];
__device__ __nv_bfloat16 g_fWXhl[1152 * 64];   // W'=[Whi|Whi|Wlo|0] per row
// bf16 transposed+split weights ([N, 2K] per t)
__device__ __nv_bfloat16 g_WT1[3 * 128 * 256];
__device__ __nv_bfloat16 g_WT2[3 * 384 * 256];
__device__ __nv_bfloat16 g_WTmix[3 * 256 * 256];
__device__ __nv_bfloat16 g_WTm1[3 * 128 * 512];
__device__ __nv_bfloat16 g_WTm2[3 * 384 * 256];

// ---------------- helpers ----------------
__device__ __forceinline__ uint32_t smem_u32(const void* p) {
    uint32_t a;
    asm("{ .reg .u64 t; cvta.to.shared.u64 t, %1; cvt.u32.u64 %0, t; }" : "=r"(a) : "l"(p));
    return a;
}
__device__ __forceinline__ void cp16(void* dst, const void* src, int sz) {
    uint32_t d = smem_u32(dst);
    asm volatile("cp.async.cg.shared.global [%0], [%1], 16, %2;\n" :: "r"(d), "l"(src), "r"(sz));
}

// ---------------- 4-stage pipelined wmma GEMM: C = act(A @ W^T + bias) ----------------
// split=1: A [M,2K] hi|lo, W [N,2K] hi|lo; 3-term bf16x3 (ksteps = 3*K/32).
// split=0: plain A [M,K] @ W [N,K]^T (ksteps = K/32) — used by FILT (terms pre-packed in K).
// CTA tile 128x128, 8 warps (4m x 2n), warp tile 32x64, BK=32.
#define TPAD 40
#define TSTG (128 * TPAD)          // elements per tile stage
#define NSTG 4
#define SMEM_WG (NSTG * TSTG * 2 * 2)  // 81920 B (A+B stages); epilogue reuses it
__global__ void __launch_bounds__(256, 2) k_wgemm(
    const __nv_bfloat16* __restrict__ A, const __nv_bfloat16* __restrict__ W,
    const float* __restrict__ bias, float* __restrict__ Cf,
    __nv_bfloat16* __restrict__ Chl, int M, int K, int N, int lda, int split, int act) {
    extern __shared__ char smem[];
    __nv_bfloat16* As = (__nv_bfloat16*)smem;        // [NSTG][TSTG]
    __nv_bfloat16* Bs = As + NSTG * TSTG;            // [NSTG][TSTG]
    int tid = threadIdx.x;
    int wid = tid >> 5;
    int m0 = blockIdx.x * 128, n0 = blockIdx.y * 128;
    int wm = wid & 3, wn = wid >> 2;

    wmma::fragment<wmma::accumulator, 16, 16, 16, float> acc[2][4];
#pragma unroll
    for (int i = 0; i < 2; i++)
#pragma unroll
        for (int j = 0; j < 4; j++) wmma::fill_fragment(acc[i][j], 0.0f);

    int kchunks = K >> 5;
    int ksteps = split ? 3 * kchunks : kchunks;
    int r_ld = tid >> 2, c8 = (tid & 3) * 8;

    auto load_stage = [&](int step, int buf) {
        int ka, kw;
        if (split) {
            int ph = step / kchunks, kb = step % kchunks;
            ka = (ph == 1 ? K : 0) + kb * 32;
            kw = (ph == 2 ? K : 0) + kb * 32;
        } else {
            ka = kw = step * 32;
        }
        __nv_bfloat16* a_dst = As + buf * TSTG;
        __nv_bfloat16* b_dst = Bs + buf * TSTG;
#pragma unroll
        for (int u = 0; u < 2; u++) {
            int r = r_ld + u * 64;
            int m = m0 + r;
            int mc = (m < M) ? m : (M - 1);
            cp16(a_dst + r * TPAD + c8, A + (size_t)mc * lda + ka + c8, (m < M) ? 16 : 0);
            cp16(b_dst + r * TPAD + c8, W + (size_t)(n0 + r) * lda + kw + c8, 16);
        }
        asm volatile("cp.async.commit_group;\n" ::: "memory");
    };

    // preload 3 groups (pad with empty commits so wait arithmetic is uniform)
#pragma unroll
    for (int s = 0; s < NSTG - 1; s++) {
        if (s < ksteps) load_stage(s, s);
        else asm volatile("cp.async.commit_group;\n" ::: "memory");
    }
    for (int step = 0; step < ksteps; step++) {
        int buf = step & (NSTG - 1);
        asm volatile("cp.async.wait_group %0;\n" :: "n"(NSTG - 2) : "memory");
        __syncthreads();
        if (step + NSTG - 1 < ksteps) load_stage(step + NSTG - 1, (step + NSTG - 1) & (NSTG - 1));
        else asm volatile("cp.async.commit_group;\n" ::: "memory");
        const __nv_bfloat16* Asb = As + buf * TSTG;
        const __nv_bfloat16* Bsb = Bs + buf * TSTG;
#pragma unroll
        for (int kk = 0; kk < 32; kk += 16) {
            wmma::fragment<wmma::matrix_a, 16, 16, 16, __nv_bfloat16, wmma::row_major> af[2];
            wmma::fragment<wmma::matrix_b, 16, 16, 16, __nv_bfloat16, wmma::col_major> bf[4];
#pragma unroll
            for (int i = 0; i < 2; i++)
                wmma::load_matrix_sync(af[i], Asb + (wm * 32 + i * 16) * TPAD + kk, TPAD);
#pragma unroll
            for (int j = 0; j < 4; j++)
                wmma::load_matrix_sync(bf[j], Bsb + (wn * 64 + j * 16) * TPAD + kk, TPAD);
#pragma unroll
            for (int i = 0; i < 2; i++)
#pragma unroll
                for (int j = 0; j < 4; j++)
                    wmma::mma_sync(acc[i][j], af[i], bf[j], acc[i][j]);
        }
    }
    asm volatile("cp.async.wait_group 0;\n" ::: "memory");
    __syncthreads();

    // single-pass epilogue: full 128x128 fp32 staged in the (free) stage area
    float* stg = (float*)smem;
#pragma unroll
    for (int i = 0; i < 2; i++)
#pragma unroll
        for (int j = 0; j < 4; j++)
            wmma::store_matrix_sync(stg + (wm * 32 + i * 16) * 128 + wn * 64 + j * 16,
                                    acc[i][j], 128, wmma::mem_row_major);
    __syncthreads();
#pragma unroll
    for (int u = 0; u < 16; u++) {
        int idx = tid + u * 256;
        int r = idx >> 5, c4 = (idx & 31) * 4;
        int m = m0 + r;
        if (m >= M) continue;
        float4 v = *(float4*)&stg[r * 128 + c4];
        int n = n0 + c4;
        if (bias) {
            v.x += bias[n + 0]; v.y += bias[n + 1];
            v.z += bias[n + 2]; v.w += bias[n + 3];
        }
        if (act) {
            v.x = v.x / (1.0f + __expf(-v.x));
            v.y = v.y / (1.0f + __expf(-v.y));
            v.z = v.z / (1.0f + __expf(-v.z));
            v.w = v.w / (1.0f + __expf(-v.w));
        }
        if (Cf) {
            *(float4*)(Cf + (size_t)m * N + n) = v;
        } else {
            __nv_bfloat16 h0 = __float2bfloat16(v.x), h1 = __float2bfloat16(v.y);
            __nv_bfloat16 h2 = __float2bfloat16(v.z), h3 = __float2bfloat16(v.w);
            __nv_bfloat16 l0 = __float2bfloat16(v.x - __bfloat162float(h0));
            __nv_bfloat16 l1 = __float2bfloat16(v.y - __bfloat162float(h1));
            __nv_bfloat16 l2 = __float2bfloat16(v.z - __bfloat162float(h2));
            __nv_bfloat16 l3 = __float2bfloat16(v.w - __bfloat162float(h3));
            __nv_bfloat16* ph = Chl + (size_t)m * 2 * N + n;
            *(__nv_bfloat162*)(ph + 0) = __nv_bfloat162(h0, h1);
            *(__nv_bfloat162*)(ph + 2) = __nv_bfloat162(h2, h3);
            __nv_bfloat16* pl = Chl + (size_t)m * 2 * N + N + n;
            *(__nv_bfloat162*)(pl + 0) = __nv_bfloat162(l0, l1);
            *(__nv_bfloat162*)(pl + 2) = __nv_bfloat162(l2, l3);
        }
    }
}

// ---------------- prep kernels ----------------
// W' rows [1152,64]: cols [0,21)=Whi, [21,42)=Whi, [42,63)=Wlo, 63=0 (fb folded at k=20)
__global__ void k_fwx(const float* __restrict__ fW, const float* __restrict__ fb) {
    int n = blockIdx.x * blockDim.x + threadIdx.x;
    if (n >= 1152) return;
    for (int k = 0; k < 21; k++) {
        float v = (k < 20) ? fW[k * 1152 + n] : fb[n];
        __nv_bfloat16 hi = __float2bfloat16(v);
        __nv_bfloat16 lo = __float2bfloat16(v - __bfloat162float(hi));
        g_fWXhl[n * 64 + k] = hi;
        g_fWXhl[n * 64 + 21 + k] = hi;
        g_fWXhl[n * 64 + 42 + k] = lo;
    }
    g_fWXhl[n * 64 + 63] = __float2bfloat16(0.0f);
}

// transpose [K,N] fp32 -> [N,2K] bf16 hi|lo, for 3 t's
__global__ void k_wsplit(const float* __restrict__ src, __nv_bfloat16* __restrict__ dst,
                         int K, int N) {
    int t = blockIdx.y;
    int id = blockIdx.x * 256 + threadIdx.x;
    if (id >= K * N) return;
    int k = id / N, n = id % N;
    float v = src[(size_t)t * K * N + (size_t)k * N + n];
    __nv_bfloat16 hi = __float2bfloat16(v);
    float lo = v - __bfloat162float(hi);
    size_t base = (size_t)t * N * 2 * K + (size_t)n * 2 * K;
    dst[base + k] = hi;
    dst[base + K + k] = __float2bfloat16(lo);
}

__global__ void k_count(const int* __restrict__ idx_i) {
    int e = blockIdx.x * blockDim.x + threadIdx.x;
    if (e < NE) atomicAdd(&g_cnt[idx_i[e]], 1);
}

__global__ void k_scan() {
    __shared__ int sm[1024];
    __shared__ int carry_s;
    int tid = threadIdx.x;
    if (tid == 0) carry_s = 0;
    __syncthreads();
    for (int base = 0; base < NA; base += 1024) {
        int idx = base + tid;
        int v = (idx < NA) ? g_cnt[idx] : 0;
        sm[tid] = v;
        __syncthreads();
        for (int off = 1; off < 1024; off <<= 1) {
            int t = (tid >= off) ? sm[tid - off] : 0;
            __syncthreads();
            sm[tid] += t;
            __syncthreads();
        }
        int out = carry_s + sm[tid] - v;
        if (idx < NA) { g_start[idx] = out; g_cursor[idx] = out; }
        int tot = sm[1023];
        __syncthreads();
        if (tid == 0) carry_s += tot;
        __syncthreads();
    }
    if (tid == 0) g_start[NA] = carry_s;
}

// A' rows [E,64]: [phi_hi(21)|phi_lo(21)|phi_hi(21)|0], fcut folded at k=20
__global__ void k_build(const float* __restrict__ pos,
                        const int* __restrict__ idx_i,
                        const int* __restrict__ idx_j) {
    int e = blockIdx.x * blockDim.x + threadIdx.x;
    if (e >= NE) return;
    int i = idx_i[e], j = idx_j[e];
    float r0 = pos[3 * j + 0] - pos[3 * i + 0];
    float r1 = pos[3 * j + 1] - pos[3 * i + 1];
    float r2 = pos[3 * j + 2] - pos[3 * i + 2];
    r0 = (fabsf(r0) < 1e-6f) ? 1e-6f : r0;
    r1 = (fabsf(r1) < 1e-6f) ? 1e-6f : r1;
    r2 = (fabsf(r2) < 1e-6f) ? 1e-6f : r2;
    float d = sqrtf(r0 * r0 + r1 * r1 + r2 * r2);
    float inv = 1.0f / d;
    float fc = (d < 5.0f) ? 0.5f * (cosf(0.628318530717959f * d) + 1.0f) : 0.0f;
    int slot = atomicAdd(&g_cursor[i], 1);
    g_js[slot] = j;
    g_eo[slot] = e;
    g_dir[3 * slot + 0] = r0 * inv;
    g_dir[3 * slot + 1] = r1 * inv;
    g_dir[3 * slot + 2] = r2 * inv;
    const float step = 5.0f / 19.0f;
    const float coeff = -7.22f;
    size_t pb = (size_t)slot * 64;
    for (int k = 0; k < 21; k++) {
        float v;
        if (k < 20) {
            float df = d - (float)k * step;
            v = expf(coeff * df * df) * fc;
        } else {
            v = fc;
        }
        __nv_bfloat16 hi = __float2bfloat16(v);
        __nv_bfloat16 lo = __float2bfloat16(v - __bfloat162float(hi));
        g_phiHL[pb + k] = hi;
        g_phiHL[pb + 21 + k] = lo;
        g_phiHL[pb + 42 + k] = hi;
    }
    g_phiHL[pb + 63] = __float2bfloat16(0.0f);
}

__global__ void k_init_q(const int* __restrict__ z, const float* __restrict__ emb) {
    int n = blockIdx.x;
    int f = threadIdx.x;
    float v = emb[(size_t)z[n] * 128 + f];
    g_q[(size_t)n * 128 + f] = v;
    __nv_bfloat16 hi = __float2bfloat16(v);
    g_qhl[(size_t)n * 256 + f] = hi;
    g_qhl[(size_t)n * 256 + 128 + f] = __float2bfloat16(v - __bfloat162float(hi));
}

// ---------------- edge aggregation (deterministic, gather-side) ----------------
#define MAXD 512
__global__ void __launch_bounds__(128) k_edge() {
    int i = blockIdx.x;
    int f = threadIdx.x;
    int s0 = g_start[i], s1 = g_start[i + 1];
    int L = s1 - s0;
    __shared__ int se[MAXD];
    __shared__ int ord[MAXD];
    bool srt = (L <= MAXD);
    if (srt && L > 0) {
        for (int a = f; a < L; a += 128) se[a] = g_eo[s0 + a];
        __syncthreads();
        for (int a = f; a < L; a += 128) {
            int my = se[a];
            int r = 0;
            for (int b = 0; b < L; b++) r += (se[b] < my);
            ord[r] = a;
        }
        __syncthreads();
    }
    float aq = 0.0f, m0 = 0.0f, m1 = 0.0f, m2 = 0.0f;
    for (int a = 0; a < L; a++) {
        int slot = s0 + (srt ? ord[a] : a);
        int j = g_js[slot];
        float d0 = g_dir[3 * slot + 0];
        float d1 = g_dir[3 * slot + 1];
        float d2 = g_dir[3 * slot + 2];
        size_t fbx = (size_t)slot * 384;
        float fq = g_filt[fbx + f];
        float fR = g_filt[fbx + 128 + f];
        float fM = g_filt[fbx + 256 + f];
        size_t xb = (size_t)j * 384;
        float xq = g_x[xb + f];
        float xR = g_x[xb + 128 + f];
        float xM = g_x[xb + 256 + f];
        float mj0 = g_muA[xb + f];
        float mj1 = g_muA[xb + 128 + f];
        float mj2 = g_muA[xb + 256 + f];
        aq += fq * xq;
        float tR = fR * xR, tM = fM * xM;
        m0 += tR * d0 + tM * mj0;
        m1 += tR * d1 + tM * mj1;
        m2 += tR * d2 + tM * mj2;
    }
    size_t mb_ = (size_t)i * 384;
    g_q[(size_t)i * 128 + f] += aq;
    float b0 = g_muA[mb_ + f] + m0;
    float b1 = g_muA[mb_ + 128 + f] + m1;
    float b2 = g_muA[mb_ + 256 + f] + m2;
    g_muB[mb_ + f] = b0;
    g_muB[mb_ + 128 + f] = b1;
    g_muB[mb_ + 256 + f] = b2;
    size_t hb = (size_t)i * 768;
    __nv_bfloat16 h0 = __float2bfloat16(b0);
    __nv_bfloat16 h1 = __float2bfloat16(b1);
    __nv_bfloat16 h2 = __float2bfloat16(b2);
    g_muBhl[hb + f] = h0;
    g_muBhl[hb + 128 + f] = __float2bfloat16(b0 - __bfloat162float(h0));
    g_muBhl[hb + 256 + f] = h1;
    g_muBhl[hb + 384 + f] = __float2bfloat16(b1 - __bfloat162float(h1));
    g_muBhl[hb + 512 + f] = h2;
    g_muBhl[hb + 640 + f] = __float2bfloat16(b2 - __bfloat162float(h2));
}

// ---------------- mixing elementwise ----------------
__global__ void k_ctx() {
    int n = blockIdx.x;
    int f = threadIdx.x;
    size_t mmb = (size_t)n * 768;
    float v0 = g_mm[mmb + f];
    float v1 = g_mm[mmb + 256 + f];
    float v2 = g_mm[mmb + 512 + f];
    float w0 = g_mm[mmb + 128 + f];
    float w1 = g_mm[mmb + 384 + f];
    float w2 = g_mm[mmb + 640 + f];
    float vn = sqrtf(v0 * v0 + v1 * v1 + v2 * v2 + 1e-8f);
    float s = v0 * w0 + v1 * w1 + v2 * w2;
    float qv = g_q[(size_t)n * 128 + f];
    size_t cb = (size_t)n * 512;
    __nv_bfloat16 qh = __float2bfloat16(qv);
    __nv_bfloat16 vh = __float2bfloat16(vn);
    g_ctxhl[cb + f] = qh;
    g_ctxhl[cb + 128 + f] = vh;
    g_ctxhl[cb + 256 + f] = __float2bfloat16(qv - __bfloat162float(qh));
    g_ctxhl[cb + 384 + f] = __float2bfloat16(vn - __bfloat162float(vh));
    g_s[(size_t)n * 128 + f] = s;
}

__global__ void k_update() {
    int n = blockIdx.x;
    int f = threadIdx.x;
    size_t xb = (size_t)n * 384;
    float dq  = g_x[xb + f];
    float dmc = g_x[xb + 128 + f];
    float dqm = g_x[xb + 256 + f];
    float qn = g_q[(size_t)n * 128 + f] + dq + dqm * g_s[(size_t)n * 128 + f];
    g_q[(size_t)n * 128 + f] = qn;
    __nv_bfloat16 qh = __float2bfloat16(qn);
    g_qhl[(size_t)n * 256 + f] = qh;
    g_qhl[(size_t)n * 256 + 128 + f] = __float2bfloat16(qn - __bfloat162float(qh));
    size_t mmb = (size_t)n * 768;
    g_muA[xb + f]       = g_muB[xb + f]       + dmc * g_mm[mmb + 128 + f];
    g_muA[xb + 128 + f] = g_muB[xb + 128 + f] + dmc * g_mm[mmb + 384 + f];
    g_muA[xb + 256 + f] = g_muB[xb + 256 + f] + dmc * g_mm[mmb + 640 + f];
}

// ---------------- launcher ----------------
extern "C" void kernel_launch(void* const* d_in, const int* in_sizes, int n_in,
                              void* d_out, int out_size) {
    const int*   z     = (const int*)d_in[0];
    const float* pos   = (const float*)d_in[1];
    const int*   idx_i = (const int*)d_in[2];
    const int*   idx_j = (const int*)d_in[3];
    const float* emb   = (const float*)d_in[4];
    const float* fW    = (const float*)d_in[5];
    const float* fb    = (const float*)d_in[6];
    const float* iW1   = (const float*)d_in[7];
    const float* ib1   = (const float*)d_in[8];
    const float* iW2   = (const float*)d_in[9];
    const float* ib2   = (const float*)d_in[10];
    const float* mWmix = (const float*)d_in[11];
    const float* mW1   = (const float*)d_in[12];
    const float* mb1   = (const float*)d_in[13];
    const float* mW2   = (const float*)d_in[14];
    const float* mb2   = (const float*)d_in[15];
    float* out = (float*)d_out;

    cudaFuncSetAttribute(k_wgemm, cudaFuncAttributeMaxDynamicSharedMemorySize, SMEM_WG);

    void *p_cnt, *p_muA, *p_q, *p_x, *p_mm, *p_filt;
    void *p_qhl, *p_hhl, *p_ctxhl, *p_muBhl, *p_phiHL, *p_fWXhl;
    void *p_WT1, *p_WT2, *p_WTmix, *p_WTm1, *p_WTm2;
    cudaGetSymbolAddress(&p_cnt, g_cnt);
    cudaGetSymbolAddress(&p_muA, g_muA);
    cudaGetSymbolAddress(&p_q, g_q);
    cudaGetSymbolAddress(&p_x, g_x);
    cudaGetSymbolAddress(&p_mm, g_mm);
    cudaGetSymbolAddress(&p_filt, g_filt);
    cudaGetSymbolAddress(&p_qhl, g_qhl);
    cudaGetSymbolAddress(&p_hhl, g_hhl);
    cudaGetSymbolAddress(&p_ctxhl, g_ctxhl);
    cudaGetSymbolAddress(&p_muBhl, g_muBhl);
    cudaGetSymbolAddress(&p_phiHL, g_phiHL);
    cudaGetSymbolAddress(&p_fWXhl, g_fWXhl);
    cudaGetSymbolAddress(&p_WT1, g_WT1);
    cudaGetSymbolAddress(&p_WT2, g_WT2);
    cudaGetSymbolAddress(&p_WTmix, g_WTmix);
    cudaGetSymbolAddress(&p_WTm1, g_WTm1);
    cudaGetSymbolAddress(&p_WTm2, g_WTm2);

    const __nv_bfloat16* qhl = (const __nv_bfloat16*)p_qhl;
    const __nv_bfloat16* hhl = (const __nv_bfloat16*)p_hhl;
    const __nv_bfloat16* ctxhl = (const __nv_bfloat16*)p_ctxhl;
    const __nv_bfloat16* muBhl = (const __nv_bfloat16*)p_muBhl;
    const __nv_bfloat16* phiHL = (const __nv_bfloat16*)p_phiHL;

    int ga = (NA + 127) / 128;       // 196
    int gm = (NA * 3 + 127) / 128;   // 586
    int ge = (NE + 127) / 128;       // 1563

    // ---- prep, ordered so the flagship GEMM is launch #6 (ncu -s 5 -c 1) ----
    cudaMemsetAsync(p_cnt, 0, NA * sizeof(int));                       // 1
    cudaMemsetAsync(p_muA, 0, (size_t)NA * 384 * sizeof(float));       // 2
    k_init_q<<<NA, 128>>>(z, emb);                                     // 3
    k_wsplit<<<dim3((128 * 128 + 255) / 256, 3), 256>>>(iW1, (__nv_bfloat16*)p_WT1, 128, 128);   // 4
    k_wsplit<<<dim3((128 * 384 + 255) / 256, 3), 256>>>(iW2, (__nv_bfloat16*)p_WT2, 128, 384);   // 5
    // H1(t=0): launch #6 -> profiled
    k_wgemm<<<dim3(ga, 1), 256, SMEM_WG>>>(
        qhl, (const __nv_bfloat16*)p_WT1, ib1, nullptr, (__nv_bfloat16*)p_hhl,
        NA, 128, 128, 256, 1, 1);
    k_wsplit<<<dim3((128 * 256 + 255) / 256, 3), 256>>>(mWmix, (__nv_bfloat16*)p_WTmix, 128, 256);
    k_wsplit<<<dim3((256 * 128 + 255) / 256, 3), 256>>>(mW1, (__nv_bfloat16*)p_WTm1, 256, 128);
    k_wsplit<<<dim3((128 * 384 + 255) / 256, 3), 256>>>(mW2, (__nv_bfloat16*)p_WTm2, 128, 384);
    k_fwx<<<(1152 + 127) / 128, 128>>>(fW, fb);
    k_count<<<(NE + 255) / 256, 256>>>(idx_i);
    k_scan<<<1, 1024>>>();
    k_build<<<(NE + 127) / 128, 128>>>(pos, idx_i, idx_j);

    for (int t = 0; t < 3; t++) {
        if (t > 0) {
            k_wgemm<<<dim3(ga, 1), 256, SMEM_WG>>>(
                qhl, (const __nv_bfloat16*)p_WT1 + (size_t)t * 128 * 256,
                ib1 + t * 128, nullptr, (__nv_bfloat16*)p_hhl, NA, 128, 128, 256, 1, 1);
        }
        // X = H1 @ iW2 + ib2 -> g_x (fp32)
        k_wgemm<<<dim3(ga, 3), 256, SMEM_WG>>>(
            hhl, (const __nv_bfloat16*)p_WT2 + (size_t)t * 384 * 256,
            ib2 + t * 384, (float*)p_x, nullptr, NA, 128, 384, 256, 1, 0);
        // FILT = phi' @ fWX'^T  (3 terms packed into K=64, plain GEMM)
        k_wgemm<<<dim3(ge, 3), 256, SMEM_WG>>>(
            phiHL, (const __nv_bfloat16*)p_fWXhl + (size_t)t * 384 * 64,
            nullptr, (float*)p_filt, nullptr, NE, 64, 384, 64, 0, 0);
        // edge aggregation
        k_edge<<<NA, 128>>>();
        // MUMIX = muB @ mWmix -> g_mm (fp32)
        k_wgemm<<<dim3(gm, 2), 256, SMEM_WG>>>(
            muBhl, (const __nv_bfloat16*)p_WTmix + (size_t)t * 256 * 256,
            nullptr, (float*)p_mm, nullptr, NA * 3, 128, 256, 256, 1, 0);
        k_ctx<<<NA, 128>>>();
        // H2 = silu(ctx @ mW1 + mb1) -> hhl   (K=256)
        k_wgemm<<<dim3(ga, 1), 256, SMEM_WG>>>(
            ctxhl, (const __nv_bfloat16*)p_WTm1 + (size_t)t * 128 * 512,
            mb1 + t * 128, nullptr, (__nv_bfloat16*)p_hhl, NA, 256, 128, 512, 1, 1);
        // X2 = H2 @ mW2 + mb2 -> g_x (fp32)
        k_wgemm<<<dim3(ga, 3), 256, SMEM_WG>>>(
            hhl, (const __nv_bfloat16*)p_WTm2 + (size_t)t * 384 * 256,
            mb2 + t * 384, (float*)p_x, nullptr, NA, 128, 384, 256, 1, 0);
        k_update<<<NA, 128>>>();
    }

    cudaMemcpyAsync(out, p_q, (size_t)NA * 128 * sizeof(float), cudaMemcpyDeviceToDevice);
    cudaMemcpyAsync(out + (size_t)NA * 128, p_muA, (size_t)NA * 384 * sizeof(float),
                    cudaMemcpyDeviceToDevice);
}

// round 13
// speedup vs baseline: 1.7746x; 1.1281x over previous
#include <cuda_runtime.h>
#include <cuda_fp16.h>
#include <mma.h>
#include <math.h>
#include <stdint.h>

using namespace nvcuda;

#define NA 25000
#define NE 200000

// ---------------- static scratch ----------------
__device__ float g_dir[(size_t)NE * 3];
__device__ int   g_js[NE];
__device__ int   g_eo[NE];
__device__ int   g_cnt[NA];
__device__ int   g_start[NA + 1];
__device__ int   g_cursor[NA];
__device__ float g_q[(size_t)NA * 128];
__device__ float g_x[(size_t)NA * 384];
__device__ float g_muA[(size_t)NA * 384];
__device__ float g_muB[(size_t)NA * 384];
__device__ float g_mm[(size_t)NA * 768];
__device__ float g_s[(size_t)NA * 128];
__device__ float g_filt[(size_t)NE * 384];
// fp16 hi/lo activation buffers ([M, 2K]: hi cols [0,K), lo cols [K,2K))
__device__ __half g_qhl[(size_t)NA * 256];
__device__ __half g_hhl[(size_t)NA * 256];
__device__ __half g_ctxhl[(size_t)NA * 512];
__device__ __half g_muBhl[(size_t)NA * 768];
// FILT operands: A'=[phi_hi(21)|phi_lo(21)|0] K=64, W'=[W|W|0]
__device__ __half g_phiHL[(size_t)NE * 64];
__device__ __half g_fWXhl[1152 * 64];
// fp16 transposed weights, K-duplicated ([N, 2K] = [W|W] per t)
__device__ __half g_WT1[3 * 128 * 256];
__device__ __half g_WT2[3 * 384 * 256];
__device__ __half g_WTmix[3 * 256 * 256];
__device__ __half g_WTm1[3 * 128 * 512];
__device__ __half g_WTm2[3 * 384 * 256];

// ---------------- helpers ----------------
__device__ __forceinline__ uint32_t smem_u32(const void* p) {
    uint32_t a;
    asm("{ .reg .u64 t; cvta.to.shared.u64 t, %1; cvt.u32.u64 %0, t; }" : "=r"(a) : "l"(p));
    return a;
}
__device__ __forceinline__ void cp16(void* dst, const void* src, int sz) {
    uint32_t d = smem_u32(dst);
    asm volatile("cp.async.cg.shared.global [%0], [%1], 16, %2;\n" :: "r"(d), "l"(src), "r"(sz));
}

// ---------------- 4-stage pipelined wmma GEMM: C = act(A @ W^T + bias) ----------------
// A: [M, K] fp16 (hi|lo packed in K).  W: [N, K] fp16 (K-duplicated).  Plain GEMM.
// CTA tile 128x128, 8 warps (4m x 2n), warp tile 32x64, BK=32.
#define TPAD 40
#define TSTG (128 * TPAD)
#define NSTG 4
#define SMEM_WG (NSTG * TSTG * 2 * 2)  // 81920 B
__global__ void __launch_bounds__(256, 2) k_wgemm(
    const __half* __restrict__ A, const __half* __restrict__ W,
    const float* __restrict__ bias, float* __restrict__ Cf,
    __half* __restrict__ Chl, int M, int K, int N, int act) {
    extern __shared__ char smem[];
    __half* As = (__half*)smem;
    __half* Bs = As + NSTG * TSTG;
    int tid = threadIdx.x;
    int wid = tid >> 5;
    int m0 = blockIdx.x * 128, n0 = blockIdx.y * 128;
    int wm = wid & 3, wn = wid >> 2;

    wmma::fragment<wmma::accumulator, 16, 16, 16, float> acc[2][4];
#pragma unroll
    for (int i = 0; i < 2; i++)
#pragma unroll
        for (int j = 0; j < 4; j++) wmma::fill_fragment(acc[i][j], 0.0f);

    int ksteps = K >> 5;
    int r_ld = tid >> 2, c8 = (tid & 3) * 8;

    auto load_stage = [&](int step, int buf) {
        int ka = step * 32;
        __half* a_dst = As + buf * TSTG;
        __half* b_dst = Bs + buf * TSTG;
#pragma unroll
        for (int u = 0; u < 2; u++) {
            int r = r_ld + u * 64;
            int m = m0 + r;
            int mc = (m < M) ? m : (M - 1);
            cp16(a_dst + r * TPAD + c8, A + (size_t)mc * K + ka + c8, (m < M) ? 16 : 0);
            cp16(b_dst + r * TPAD + c8, W + (size_t)(n0 + r) * K + ka + c8, 16);
        }
        asm volatile("cp.async.commit_group;\n" ::: "memory");
    };

#pragma unroll
    for (int s = 0; s < NSTG - 1; s++) {
        if (s < ksteps) load_stage(s, s);
        else asm volatile("cp.async.commit_group;\n" ::: "memory");
    }
    for (int step = 0; step < ksteps; step++) {
        int buf = step & (NSTG - 1);
        asm volatile("cp.async.wait_group %0;\n" :: "n"(NSTG - 2) : "memory");
        __syncthreads();
        if (step + NSTG - 1 < ksteps) load_stage(step + NSTG - 1, (step + NSTG - 1) & (NSTG - 1));
        else asm volatile("cp.async.commit_group;\n" ::: "memory");
        const __half* Asb = As + buf * TSTG;
        const __half* Bsb = Bs + buf * TSTG;
#pragma unroll
        for (int kk = 0; kk < 32; kk += 16) {
            wmma::fragment<wmma::matrix_a, 16, 16, 16, __half, wmma::row_major> af[2];
            wmma::fragment<wmma::matrix_b, 16, 16, 16, __half, wmma::col_major> bf[4];
#pragma unroll
            for (int i = 0; i < 2; i++)
                wmma::load_matrix_sync(af[i], Asb + (wm * 32 + i * 16) * TPAD + kk, TPAD);
#pragma unroll
            for (int j = 0; j < 4; j++)
                wmma::load_matrix_sync(bf[j], Bsb + (wn * 64 + j * 16) * TPAD + kk, TPAD);
#pragma unroll
            for (int i = 0; i < 2; i++)
#pragma unroll
                for (int j = 0; j < 4; j++)
                    wmma::mma_sync(acc[i][j], af[i], bf[j], acc[i][j]);
        }
    }
    asm volatile("cp.async.wait_group 0;\n" ::: "memory");
    __syncthreads();

    // single-pass epilogue: full 128x128 fp32 staged in the (free) stage area
    float* stg = (float*)smem;
#pragma unroll
    for (int i = 0; i < 2; i++)
#pragma unroll
        for (int j = 0; j < 4; j++)
            wmma::store_matrix_sync(stg + (wm * 32 + i * 16) * 128 + wn * 64 + j * 16,
                                    acc[i][j], 128, wmma::mem_row_major);
    __syncthreads();
#pragma unroll
    for (int u = 0; u < 16; u++) {
        int idx = tid + u * 256;
        int r = idx >> 5, c4 = (idx & 31) * 4;
        int m = m0 + r;
        if (m >= M) continue;
        float4 v = *(float4*)&stg[r * 128 + c4];
        int n = n0 + c4;
        if (bias) {
            v.x += bias[n + 0]; v.y += bias[n + 1];
            v.z += bias[n + 2]; v.w += bias[n + 3];
        }
        if (act) {
            v.x = v.x / (1.0f + __expf(-v.x));
            v.y = v.y / (1.0f + __expf(-v.y));
            v.z = v.z / (1.0f + __expf(-v.z));
            v.w = v.w / (1.0f + __expf(-v.w));
        }
        if (Cf) {
            *(float4*)(Cf + (size_t)m * N + n) = v;
        } else {
            __half h0 = __float2half(v.x), h1 = __float2half(v.y);
            __half h2 = __float2half(v.z), h3 = __float2half(v.w);
            __half l0 = __float2half(v.x - __half2float(h0));
            __half l1 = __float2half(v.y - __half2float(h1));
            __half l2 = __float2half(v.z - __half2float(h2));
            __half l3 = __float2half(v.w - __half2float(h3));
            __half* ph = Chl + (size_t)m * 2 * N + n;
            *(__half2*)(ph + 0) = __half2(h0, h1);
            *(__half2*)(ph + 2) = __half2(h2, h3);
            __half* pl = Chl + (size_t)m * 2 * N + N + n;
            *(__half2*)(pl + 0) = __half2(l0, l1);
            *(__half2*)(pl + 2) = __half2(l2, l3);
        }
    }
}

// ---------------- prep kernels ----------------
// W' rows [1152,64]: cols [0,21)=W, [21,42)=W, [42,64)=0 (fb folded at k=20)
__global__ void k_fwx(const float* __restrict__ fW, const float* __restrict__ fb) {
    int n = blockIdx.x * blockDim.x + threadIdx.x;
    if (n >= 1152) return;
    for (int k = 0; k < 21; k++) {
        float v = (k < 20) ? fW[k * 1152 + n] : fb[n];
        __half h = __float2half(v);
        g_fWXhl[n * 64 + k] = h;
        g_fWXhl[n * 64 + 21 + k] = h;
    }
    for (int k = 42; k < 64; k++) g_fWXhl[n * 64 + k] = __float2half(0.0f);
}

// transpose [K,N] fp32 -> [N,2K] fp16 K-duplicated [W|W], for 3 t's
__global__ void k_wsplit(const float* __restrict__ src, __half* __restrict__ dst,
                         int K, int N) {
    int t = blockIdx.y;
    int id = blockIdx.x * 256 + threadIdx.x;
    if (id >= K * N) return;
    int k = id / N, n = id % N;
    float v = src[(size_t)t * K * N + (size_t)k * N + n];
    __half h = __float2half(v);
    size_t base = (size_t)t * N * 2 * K + (size_t)n * 2 * K;
    dst[base + k] = h;
    dst[base + K + k] = h;
}

__global__ void k_count(const int* __restrict__ idx_i) {
    int e = blockIdx.x * blockDim.x + threadIdx.x;
    if (e < NE) atomicAdd(&g_cnt[idx_i[e]], 1);
}

__global__ void k_scan() {
    __shared__ int sm[1024];
    __shared__ int carry_s;
    int tid = threadIdx.x;
    if (tid == 0) carry_s = 0;
    __syncthreads();
    for (int base = 0; base < NA; base += 1024) {
        int idx = base + tid;
        int v = (idx < NA) ? g_cnt[idx] : 0;
        sm[tid] = v;
        __syncthreads();
        for (int off = 1; off < 1024; off <<= 1) {
            int t = (tid >= off) ? sm[tid - off] : 0;
            __syncthreads();
            sm[tid] += t;
            __syncthreads();
        }
        int out = carry_s + sm[tid] - v;
        if (idx < NA) { g_start[idx] = out; g_cursor[idx] = out; }
        int tot = sm[1023];
        __syncthreads();
        if (tid == 0) carry_s += tot;
        __syncthreads();
    }
    if (tid == 0) g_start[NA] = carry_s;
}

// A' rows [E,64]: [phi_hi(21)|phi_lo(21)|0], fcut folded at k=20
__global__ void k_build(const float* __restrict__ pos,
                        const int* __restrict__ idx_i,
                        const int* __restrict__ idx_j) {
    int e = blockIdx.x * blockDim.x + threadIdx.x;
    if (e >= NE) return;
    int i = idx_i[e], j = idx_j[e];
    float r0 = pos[3 * j + 0] - pos[3 * i + 0];
    float r1 = pos[3 * j + 1] - pos[3 * i + 1];
    float r2 = pos[3 * j + 2] - pos[3 * i + 2];
    r0 = (fabsf(r0) < 1e-6f) ? 1e-6f : r0;
    r1 = (fabsf(r1) < 1e-6f) ? 1e-6f : r1;
    r2 = (fabsf(r2) < 1e-6f) ? 1e-6f : r2;
    float d = sqrtf(r0 * r0 + r1 * r1 + r2 * r2);
    float inv = 1.0f / d;
    float fc = (d < 5.0f) ? 0.5f * (cosf(0.628318530717959f * d) + 1.0f) : 0.0f;
    int slot = atomicAdd(&g_cursor[i], 1);
    g_js[slot] = j;
    g_eo[slot] = e;
    g_dir[3 * slot + 0] = r0 * inv;
    g_dir[3 * slot + 1] = r1 * inv;
    g_dir[3 * slot + 2] = r2 * inv;
    const float step = 5.0f / 19.0f;
    const float coeff = -7.22f;
    size_t pb = (size_t)slot * 64;
    for (int k = 0; k < 21; k++) {
        float v;
        if (k < 20) {
            float df = d - (float)k * step;
            v = expf(coeff * df * df) * fc;
        } else {
            v = fc;
        }
        __half h = __float2half(v);
        g_phiHL[pb + k] = h;
        g_phiHL[pb + 21 + k] = __float2half(v - __half2float(h));
    }
    for (int k = 42; k < 64; k++) g_phiHL[pb + k] = __float2half(0.0f);
}

__global__ void k_init_q(const int* __restrict__ z, const float* __restrict__ emb) {
    int n = blockIdx.x;
    int f = threadIdx.x;
    float v = emb[(size_t)z[n] * 128 + f];
    g_q[(size_t)n * 128 + f] = v;
    __half h = __float2half(v);
    g_qhl[(size_t)n * 256 + f] = h;
    g_qhl[(size_t)n * 256 + 128 + f] = __float2half(v - __half2float(h));
}

// ---------------- edge aggregation (deterministic, gather-side) ----------------
#define MAXD 512
__global__ void __launch_bounds__(128) k_edge() {
    int i = blockIdx.x;
    int f = threadIdx.x;
    int s0 = g_start[i], s1 = g_start[i + 1];
    int L = s1 - s0;
    __shared__ int se[MAXD];
    __shared__ int ord[MAXD];
    bool srt = (L <= MAXD);
    if (srt && L > 0) {
        for (int a = f; a < L; a += 128) se[a] = g_eo[s0 + a];
        __syncthreads();
        for (int a = f; a < L; a += 128) {
            int my = se[a];
            int r = 0;
            for (int b = 0; b < L; b++) r += (se[b] < my);
            ord[r] = a;
        }
        __syncthreads();
    }
    float aq = 0.0f, m0 = 0.0f, m1 = 0.0f, m2 = 0.0f;
    for (int a = 0; a < L; a++) {
        int slot = s0 + (srt ? ord[a] : a);
        int j = g_js[slot];
        float d0 = g_dir[3 * slot + 0];
        float d1 = g_dir[3 * slot + 1];
        float d2 = g_dir[3 * slot + 2];
        size_t fbx = (size_t)slot * 384;
        float fq = g_filt[fbx + f];
        float fR = g_filt[fbx + 128 + f];
        float fM = g_filt[fbx + 256 + f];
        size_t xb = (size_t)j * 384;
        float xq = g_x[xb + f];
        float xR = g_x[xb + 128 + f];
        float xM = g_x[xb + 256 + f];
        float mj0 = g_muA[xb + f];
        float mj1 = g_muA[xb + 128 + f];
        float mj2 = g_muA[xb + 256 + f];
        aq += fq * xq;
        float tR = fR * xR, tM = fM * xM;
        m0 += tR * d0 + tM * mj0;
        m1 += tR * d1 + tM * mj1;
        m2 += tR * d2 + tM * mj2;
    }
    size_t mb_ = (size_t)i * 384;
    g_q[(size_t)i * 128 + f] += aq;
    float b0 = g_muA[mb_ + f] + m0;
    float b1 = g_muA[mb_ + 128 + f] + m1;
    float b2 = g_muA[mb_ + 256 + f] + m2;
    g_muB[mb_ + f] = b0;
    g_muB[mb_ + 128 + f] = b1;
    g_muB[mb_ + 256 + f] = b2;
    size_t hb = (size_t)i * 768;
    __half h0 = __float2half(b0);
    __half h1 = __float2half(b1);
    __half h2 = __float2half(b2);
    g_muBhl[hb + f] = h0;
    g_muBhl[hb + 128 + f] = __float2half(b0 - __half2float(h0));
    g_muBhl[hb + 256 + f] = h1;
    g_muBhl[hb + 384 + f] = __float2half(b1 - __half2float(h1));
    g_muBhl[hb + 512 + f] = h2;
    g_muBhl[hb + 640 + f] = __float2half(b2 - __half2float(h2));
}

// ---------------- mixing elementwise ----------------
__global__ void k_ctx() {
    int n = blockIdx.x;
    int f = threadIdx.x;
    size_t mmb = (size_t)n * 768;
    float v0 = g_mm[mmb + f];
    float v1 = g_mm[mmb + 256 + f];
    float v2 = g_mm[mmb + 512 + f];
    float w0 = g_mm[mmb + 128 + f];
    float w1 = g_mm[mmb + 384 + f];
    float w2 = g_mm[mmb + 640 + f];
    float vn = sqrtf(v0 * v0 + v1 * v1 + v2 * v2 + 1e-8f);
    float s = v0 * w0 + v1 * w1 + v2 * w2;
    float qv = g_q[(size_t)n * 128 + f];
    size_t cb = (size_t)n * 512;
    __half qh = __float2half(qv);
    __half vh = __float2half(vn);
    g_ctxhl[cb + f] = qh;
    g_ctxhl[cb + 128 + f] = vh;
    g_ctxhl[cb + 256 + f] = __float2half(qv - __half2float(qh));
    g_ctxhl[cb + 384 + f] = __float2half(vn - __half2float(vh));
    g_s[(size_t)n * 128 + f] = s;
}

__global__ void k_update() {
    int n = blockIdx.x;
    int f = threadIdx.x;
    size_t xb = (size_t)n * 384;
    float dq  = g_x[xb + f];
    float dmc = g_x[xb + 128 + f];
    float dqm = g_x[xb + 256 + f];
    float qn = g_q[(size_t)n * 128 + f] + dq + dqm * g_s[(size_t)n * 128 + f];
    g_q[(size_t)n * 128 + f] = qn;
    __half qh = __float2half(qn);
    g_qhl[(size_t)n * 256 + f] = qh;
    g_qhl[(size_t)n * 256 + 128 + f] = __float2half(qn - __half2float(qh));
    size_t mmb = (size_t)n * 768;
    g_muA[xb + f]       = g_muB[xb + f]       + dmc * g_mm[mmb + 128 + f];
    g_muA[xb + 128 + f] = g_muB[xb + 128 + f] + dmc * g_mm[mmb + 384 + f];
    g_muA[xb + 256 + f] = g_muB[xb + 256 + f] + dmc * g_mm[mmb + 640 + f];
}

// ---------------- launcher ----------------
extern "C" void kernel_launch(void* const* d_in, const int* in_sizes, int n_in,
                              void* d_out, int out_size) {
    const int*   z     = (const int*)d_in[0];
    const float* pos   = (const float*)d_in[1];
    const int*   idx_i = (const int*)d_in[2];
    const int*   idx_j = (const int*)d_in[3];
    const float* emb   = (const float*)d_in[4];
    const float* fW    = (const float*)d_in[5];
    const float* fb    = (const float*)d_in[6];
    const float* iW1   = (const float*)d_in[7];
    const float* ib1   = (const float*)d_in[8];
    const float* iW2   = (const float*)d_in[9];
    const float* ib2   = (const float*)d_in[10];
    const float* mWmix = (const float*)d_in[11];
    const float* mW1   = (const float*)d_in[12];
    const float* mb1   = (const float*)d_in[13];
    const float* mW2   = (const float*)d_in[14];
    const float* mb2   = (const float*)d_in[15];
    float* out = (float*)d_out;

    cudaFuncSetAttribute(k_wgemm, cudaFuncAttributeMaxDynamicSharedMemorySize, SMEM_WG);

    void *p_cnt, *p_muA, *p_q, *p_x, *p_mm, *p_filt;
    void *p_qhl, *p_hhl, *p_ctxhl, *p_muBhl, *p_phiHL, *p_fWXhl;
    void *p_WT1, *p_WT2, *p_WTmix, *p_WTm1, *p_WTm2;
    cudaGetSymbolAddress(&p_cnt, g_cnt);
    cudaGetSymbolAddress(&p_muA, g_muA);
    cudaGetSymbolAddress(&p_q, g_q);
    cudaGetSymbolAddress(&p_x, g_x);
    cudaGetSymbolAddress(&p_mm, g_mm);
    cudaGetSymbolAddress(&p_filt, g_filt);
    cudaGetSymbolAddress(&p_qhl, g_qhl);
    cudaGetSymbolAddress(&p_hhl, g_hhl);
    cudaGetSymbolAddress(&p_ctxhl, g_ctxhl);
    cudaGetSymbolAddress(&p_muBhl, g_muBhl);
    cudaGetSymbolAddress(&p_phiHL, g_phiHL);
    cudaGetSymbolAddress(&p_fWXhl, g_fWXhl);
    cudaGetSymbolAddress(&p_WT1, g_WT1);
    cudaGetSymbolAddress(&p_WT2, g_WT2);
    cudaGetSymbolAddress(&p_WTmix, g_WTmix);
    cudaGetSymbolAddress(&p_WTm1, g_WTm1);
    cudaGetSymbolAddress(&p_WTm2, g_WTm2);

    const __half* qhl = (const __half*)p_qhl;
    const __half* hhl = (const __half*)p_hhl;
    const __half* ctxhl = (const __half*)p_ctxhl;
    const __half* muBhl = (const __half*)p_muBhl;
    const __half* phiHL = (const __half*)p_phiHL;

    int ga = (NA + 127) / 128;       // 196
    int gm = (NA * 3 + 127) / 128;   // 586
    int ge = (NE + 127) / 128;       // 1563

    // ---- prep, ordered so the flagship GEMM is launch #6 (ncu -s 5 -c 1) ----
    cudaMemsetAsync(p_cnt, 0, NA * sizeof(int));                       // 1
    cudaMemsetAsync(p_muA, 0, (size_t)NA * 384 * sizeof(float));       // 2
    k_init_q<<<NA, 128>>>(z, emb);                                     // 3
    k_wsplit<<<dim3((128 * 128 + 255) / 256, 3), 256>>>(iW1, (__half*)p_WT1, 128, 128);   // 4
    k_wsplit<<<dim3((128 * 384 + 255) / 256, 3), 256>>>(iW2, (__half*)p_WT2, 128, 384);   // 5
    // H1(t=0): launch #6 -> profiled
    k_wgemm<<<dim3(ga, 1), 256, SMEM_WG>>>(
        qhl, (const __half*)p_WT1, ib1, nullptr, (__half*)p_hhl, NA, 256, 128, 1);
    k_wsplit<<<dim3((128 * 256 + 255) / 256, 3), 256>>>(mWmix, (__half*)p_WTmix, 128, 256);
    k_wsplit<<<dim3((256 * 128 + 255) / 256, 3), 256>>>(mW1, (__half*)p_WTm1, 256, 128);
    k_wsplit<<<dim3((128 * 384 + 255) / 256, 3), 256>>>(mW2, (__half*)p_WTm2, 128, 384);
    k_fwx<<<(1152 + 127) / 128, 128>>>(fW, fb);
    k_count<<<(NE + 255) / 256, 256>>>(idx_i);
    k_scan<<<1, 1024>>>();
    k_build<<<(NE + 127) / 128, 128>>>(pos, idx_i, idx_j);

    for (int t = 0; t < 3; t++) {
        if (t > 0) {
            k_wgemm<<<dim3(ga, 1), 256, SMEM_WG>>>(
                qhl, (const __half*)p_WT1 + (size_t)t * 128 * 256,
                ib1 + t * 128, nullptr, (__half*)p_hhl, NA, 256, 128, 1);
        }
        // X = H1 @ iW2 + ib2 -> g_x (fp32)
        k_wgemm<<<dim3(ga, 3), 256, SMEM_WG>>>(
            hhl, (const __half*)p_WT2 + (size_t)t * 384 * 256,
            ib2 + t * 384, (float*)p_x, nullptr, NA, 256, 384, 0);
        // FILT = phi' @ fWX'^T  (2 terms packed into K=64)
        k_wgemm<<<dim3(ge, 3), 256, SMEM_WG>>>(
            phiHL, (const __half*)p_fWXhl + (size_t)t * 384 * 64,
            nullptr, (float*)p_filt, nullptr, NE, 64, 384, 0);
        // edge aggregation
        k_edge<<<NA, 128>>>();
        // MUMIX = muB @ mWmix -> g_mm (fp32)
        k_wgemm<<<dim3(gm, 2), 256, SMEM_WG>>>(
            muBhl, (const __half*)p_WTmix + (size_t)t * 256 * 256,
            nullptr, (float*)p_mm, nullptr, NA * 3, 256, 256, 0);
        k_ctx<<<NA, 128>>>();
        // H2 = silu(ctx @ mW1 + mb1) -> hhl   (K=512 packed)
        k_wgemm<<<dim3(ga, 1), 256, SMEM_WG>>>(
            ctxhl, (const __half*)p_WTm1 + (size_t)t * 128 * 512,
            mb1 + t * 128, nullptr, (__half*)p_hhl, NA, 512, 128, 1);
        // X2 = H2 @ mW2 + mb2 -> g_x (fp32)
        k_wgemm<<<dim3(ga, 3), 256, SMEM_WG>>>(
            hhl, (const __half*)p_WTm2 + (size_t)t * 384 * 256,
            mb2 + t * 384, (float*)p_x, nullptr, NA, 256, 384, 0);
        k_update<<<NA, 128>>>();
    }

    cudaMemcpyAsync(out, p_q, (size_t)NA * 128 * sizeof(float), cudaMemcpyDeviceToDevice);
    cudaMemcpyAsync(out + (size_t)NA * 128, p_muA, (size_t)NA * 384 * sizeof(float),
                    cudaMemcpyDeviceToDevice);
}

// round 15
// speedup vs baseline: 1.8835x; 1.0614x over previous
#include <cuda_runtime.h>
#include <cuda_fp16.h>
#include <mma.h>
#include <math.h>
#include <stdint.h>

using namespace nvcuda;

#define NA 25000
#define NE 200000

// ---------------- static scratch ----------------
__device__ float g_dir[(size_t)NE * 3];
__device__ int   g_js[NE];
__device__ int   g_eo[NE];
__device__ int   g_cnt[NA];
__device__ int   g_start[NA + 1];
__device__ int   g_cursor[NA];
__device__ float g_q[(size_t)NA * 128];
__device__ float g_x[(size_t)NA * 384];       // X2 result (fp32, feeds k_update)
__device__ __half g_xh[(size_t)NA * 384];     // X  result (fp16, feeds k_edge)
__device__ float g_muA[(size_t)NA * 384];
__device__ float g_muB[(size_t)NA * 384];
__device__ float g_mm[(size_t)NA * 768];
__device__ float g_s[(size_t)NA * 128];
__device__ __half g_filth[(size_t)NE * 384];  // FILT result (fp16, feeds k_edge)
// fp16 hi/lo activation buffers ([M, 2K]: hi cols [0,K), lo cols [K,2K))
__device__ __half g_qhl[(size_t)NA * 256];
__device__ __half g_hhl[(size_t)NA * 256];
__device__ __half g_ctxhl[(size_t)NA * 512];
__device__ __half g_muBhl[(size_t)NA * 768];
// FILT operands: A'=[phi_hi(21)|phi_lo(21)|0] K=64, W'=[W|W|0]
__device__ __half g_phiHL[(size_t)NE * 64];
__device__ __half g_fWXhl[1152 * 64];
// fp16 transposed weights, K-duplicated ([N, 2K] = [W|W] per t)
__device__ __half g_WT1[3 * 128 * 256];
__device__ __half g_WT2[3 * 384 * 256];
__device__ __half g_WTmix[3 * 256 * 256];
__device__ __half g_WTm1[3 * 128 * 512];
__device__ __half g_WTm2[3 * 384 * 256];

// ---------------- helpers ----------------
__device__ __forceinline__ uint32_t smem_u32(const void* p) {
    uint32_t a;
    asm("{ .reg .u64 t; cvta.to.shared.u64 t, %1; cvt.u32.u64 %0, t; }" : "=r"(a) : "l"(p));
    return a;
}
__device__ __forceinline__ void cp16(void* dst, const void* src, int sz) {
    uint32_t d = smem_u32(dst);
    asm volatile("cp.async.cg.shared.global [%0], [%1], 16, %2;\n" :: "r"(d), "l"(src), "r"(sz));
}

// ---------------- 4-stage pipelined wmma GEMM: C = act(A @ W^T + bias) ----------------
// A: [M, K] fp16 (hi|lo packed in K).  W: [N, K] fp16 (K-duplicated).  Plain GEMM.
// CTA tile 128x128, 8 warps (4m x 2n), warp tile 32x64, BK=32.
// outmode: 0 = fp32 Cf [M,N]; 1 = hi|lo half Chl [M,2N]; 2 = plain half Chl [M,N].
#define TPAD 40
#define TSTG (128 * TPAD)
#define NSTG 4
#define SMEM_WG (NSTG * TSTG * 2 * 2)  // 81920 B
__global__ void __launch_bounds__(256, 2) k_wgemm(
    const __half* __restrict__ A, const __half* __restrict__ W,
    const float* __restrict__ bias, float* __restrict__ Cf,
    __half* __restrict__ Chl, int M, int K, int N, int outmode, int act) {
    extern __shared__ char smem[];
    __half* As = (__half*)smem;
    __half* Bs = As + NSTG * TSTG;
    int tid = threadIdx.x;
    int wid = tid >> 5;
    int m0 = blockIdx.x * 128, n0 = blockIdx.y * 128;
    int wm = wid & 3, wn = wid >> 2;

    wmma::fragment<wmma::accumulator, 16, 16, 16, float> acc[2][4];
#pragma unroll
    for (int i = 0; i < 2; i++)
#pragma unroll
        for (int j = 0; j < 4; j++) wmma::fill_fragment(acc[i][j], 0.0f);

    int ksteps = K >> 5;
    int r_ld = tid >> 2, c8 = (tid & 3) * 8;

    auto load_stage = [&](int step, int buf) {
        int ka = step * 32;
        __half* a_dst = As + buf * TSTG;
        __half* b_dst = Bs + buf * TSTG;
#pragma unroll
        for (int u = 0; u < 2; u++) {
            int r = r_ld + u * 64;
            int m = m0 + r;
            int mc = (m < M) ? m : (M - 1);
            cp16(a_dst + r * TPAD + c8, A + (size_t)mc * K + ka + c8, (m < M) ? 16 : 0);
            cp16(b_dst + r * TPAD + c8, W + (size_t)(n0 + r) * K + ka + c8, 16);
        }
        asm volatile("cp.async.commit_group;\n" ::: "memory");
    };

#pragma unroll
    for (int s = 0; s < NSTG - 1; s++) {
        if (s < ksteps) load_stage(s, s);
        else asm volatile("cp.async.commit_group;\n" ::: "memory");
    }
    for (int step = 0; step < ksteps; step++) {
        int buf = step & (NSTG - 1);
        asm volatile("cp.async.wait_group %0;\n" :: "n"(NSTG - 2) : "memory");
        __syncthreads();
        if (step + NSTG - 1 < ksteps) load_stage(step + NSTG - 1, (step + NSTG - 1) & (NSTG - 1));
        else asm volatile("cp.async.commit_group;\n" ::: "memory");
        const __half* Asb = As + buf * TSTG;
        const __half* Bsb = Bs + buf * TSTG;
#pragma unroll
        for (int kk = 0; kk < 32; kk += 16) {
            wmma::fragment<wmma::matrix_a, 16, 16, 16, __half, wmma::row_major> af[2];
            wmma::fragment<wmma::matrix_b, 16, 16, 16, __half, wmma::col_major> bf[4];
#pragma unroll
            for (int i = 0; i < 2; i++)
                wmma::load_matrix_sync(af[i], Asb + (wm * 32 + i * 16) * TPAD + kk, TPAD);
#pragma unroll
            for (int j = 0; j < 4; j++)
                wmma::load_matrix_sync(bf[j], Bsb + (wn * 64 + j * 16) * TPAD + kk, TPAD);
#pragma unroll
            for (int i = 0; i < 2; i++)
#pragma unroll
                for (int j = 0; j < 4; j++)
                    wmma::mma_sync(acc[i][j], af[i], bf[j], acc[i][j]);
        }
    }
    asm volatile("cp.async.wait_group 0;\n" ::: "memory");
    __syncthreads();

    // single-pass epilogue: full 128x128 fp32 staged in the (free) stage area
    float* stg = (float*)smem;
#pragma unroll
    for (int i = 0; i < 2; i++)
#pragma unroll
        for (int j = 0; j < 4; j++)
            wmma::store_matrix_sync(stg + (wm * 32 + i * 16) * 128 + wn * 64 + j * 16,
                                    acc[i][j], 128, wmma::mem_row_major);
    __syncthreads();
#pragma unroll
    for (int u = 0; u < 16; u++) {
        int idx = tid + u * 256;
        int r = idx >> 5, c4 = (idx & 31) * 4;
        int m = m0 + r;
        if (m >= M) continue;
        float4 v = *(float4*)&stg[r * 128 + c4];
        int n = n0 + c4;
        if (bias) {
            v.x += bias[n + 0]; v.y += bias[n + 1];
            v.z += bias[n + 2]; v.w += bias[n + 3];
        }
        if (act) {
            v.x = v.x / (1.0f + __expf(-v.x));
            v.y = v.y / (1.0f + __expf(-v.y));
            v.z = v.z / (1.0f + __expf(-v.z));
            v.w = v.w / (1.0f + __expf(-v.w));
        }
        if (outmode == 0) {
            *(float4*)(Cf + (size_t)m * N + n) = v;
        } else if (outmode == 2) {
            __half2 p0 = __half2(__float2half(v.x), __float2half(v.y));
            __half2 p1 = __half2(__float2half(v.z), __float2half(v.w));
            __half* pd = Chl + (size_t)m * N + n;
            *(__half2*)(pd + 0) = p0;
            *(__half2*)(pd + 2) = p1;
        } else {
            __half h0 = __float2half(v.x), h1 = __float2half(v.y);
            __half h2 = __float2half(v.z), h3 = __float2half(v.w);
            __half l0 = __float2half(v.x - __half2float(h0));
            __half l1 = __float2half(v.y - __half2float(h1));
            __half l2 = __float2half(v.z - __half2float(h2));
            __half l3 = __float2half(v.w - __half2float(h3));
            __half* ph = Chl + (size_t)m * 2 * N + n;
            *(__half2*)(ph + 0) = __half2(h0, h1);
            *(__half2*)(ph + 2) = __half2(h2, h3);
            __half* pl = Chl + (size_t)m * 2 * N + N + n;
            *(__half2*)(pl + 0) = __half2(l0, l1);
            *(__half2*)(pl + 2) = __half2(l2, l3);
        }
    }
}

// ---------------- prep kernels ----------------
// W' rows [1152,64]: cols [0,21)=W, [21,42)=W, [42,64)=0 (fb folded at k=20)
__global__ void k_fwx(const float* __restrict__ fW, const float* __restrict__ fb) {
    int n = blockIdx.x * blockDim.x + threadIdx.x;
    if (n >= 1152) return;
    for (int k = 0; k < 21; k++) {
        float v = (k < 20) ? fW[k * 1152 + n] : fb[n];
        __half h = __float2half(v);
        g_fWXhl[n * 64 + k] = h;
        g_fWXhl[n * 64 + 21 + k] = h;
    }
    for (int k = 42; k < 64; k++) g_fWXhl[n * 64 + k] = __float2half(0.0f);
}

// transpose [K,N] fp32 -> [N,2K] fp16 K-duplicated [W|W], for 3 t's
__global__ void k_wsplit(const float* __restrict__ src, __half* __restrict__ dst,
                         int K, int N) {
    int t = blockIdx.y;
    int id = blockIdx.x * 256 + threadIdx.x;
    if (id >= K * N) return;
    int k = id / N, n = id % N;
    float v = src[(size_t)t * K * N + (size_t)k * N + n];
    __half h = __float2half(v);
    size_t base = (size_t)t * N * 2 * K + (size_t)n * 2 * K;
    dst[base + k] = h;
    dst[base + K + k] = h;
}

__global__ void k_count(const int* __restrict__ idx_i) {
    int e = blockIdx.x * blockDim.x + threadIdx.x;
    if (e < NE) atomicAdd(&g_cnt[idx_i[e]], 1);
}

__global__ void k_scan() {
    __shared__ int sm[1024];
    __shared__ int carry_s;
    int tid = threadIdx.x;
    if (tid == 0) carry_s = 0;
    __syncthreads();
    for (int base = 0; base < NA; base += 1024) {
        int idx = base + tid;
        int v = (idx < NA) ? g_cnt[idx] : 0;
        sm[tid] = v;
        __syncthreads();
        for (int off = 1; off < 1024; off <<= 1) {
            int t = (tid >= off) ? sm[tid - off] : 0;
            __syncthreads();
            sm[tid] += t;
            __syncthreads();
        }
        int out = carry_s + sm[tid] - v;
        if (idx < NA) { g_start[idx] = out; g_cursor[idx] = out; }
        int tot = sm[1023];
        __syncthreads();
        if (tid == 0) carry_s += tot;
        __syncthreads();
    }
    if (tid == 0) g_start[NA] = carry_s;
}

// A' rows [E,64]: [phi_hi(21)|phi_lo(21)|0], fcut folded at k=20
__global__ void k_build(const float* __restrict__ pos,
                        const int* __restrict__ idx_i,
                        const int* __restrict__ idx_j) {
    int e = blockIdx.x * blockDim.x + threadIdx.x;
    if (e >= NE) return;
    int i = idx_i[e], j = idx_j[e];
    float r0 = pos[3 * j + 0] - pos[3 * i + 0];
    float r1 = pos[3 * j + 1] - pos[3 * i + 1];
    float r2 = pos[3 * j + 2] - pos[3 * i + 2];
    r0 = (fabsf(r0) < 1e-6f) ? 1e-6f : r0;
    r1 = (fabsf(r1) < 1e-6f) ? 1e-6f : r1;
    r2 = (fabsf(r2) < 1e-6f) ? 1e-6f : r2;
    float d = sqrtf(r0 * r0 + r1 * r1 + r2 * r2);
    float inv = 1.0f / d;
    float fc = (d < 5.0f) ? 0.5f * (cosf(0.628318530717959f * d) + 1.0f) : 0.0f;
    int slot = atomicAdd(&g_cursor[i], 1);
    g_js[slot] = j;
    g_eo[slot] = e;
    g_dir[3 * slot + 0] = r0 * inv;
    g_dir[3 * slot + 1] = r1 * inv;
    g_dir[3 * slot + 2] = r2 * inv;
    const float step = 5.0f / 19.0f;
    const float coeff = -7.22f;
    size_t pb = (size_t)slot * 64;
    for (int k = 0; k < 21; k++) {
        float v;
        if (k < 20) {
            float df = d - (float)k * step;
            v = expf(coeff * df * df) * fc;
        } else {
            v = fc;
        }
        __half h = __float2half(v);
        g_phiHL[pb + k] = h;
        g_phiHL[pb + 21 + k] = __float2half(v - __half2float(h));
    }
    for (int k = 42; k < 64; k++) g_phiHL[pb + k] = __float2half(0.0f);
}

__global__ void k_init_q(const int* __restrict__ z, const float* __restrict__ emb) {
    int n = blockIdx.x;
    int f = threadIdx.x;
    float v = emb[(size_t)z[n] * 128 + f];
    g_q[(size_t)n * 128 + f] = v;
    __half h = __float2half(v);
    g_qhl[(size_t)n * 256 + f] = h;
    g_qhl[(size_t)n * 256 + 128 + f] = __float2half(v - __half2float(h));
}

// ---------------- edge aggregation (deterministic, gather-side) ----------------
#define MAXD 512
__global__ void __launch_bounds__(128) k_edge() {
    int i = blockIdx.x;
    int f = threadIdx.x;
    int s0 = g_start[i], s1 = g_start[i + 1];
    int L = s1 - s0;
    __shared__ int se[MAXD];
    __shared__ int ord[MAXD];
    bool srt = (L <= MAXD);
    if (srt && L > 0) {
        for (int a = f; a < L; a += 128) se[a] = g_eo[s0 + a];
        __syncthreads();
        for (int a = f; a < L; a += 128) {
            int my = se[a];
            int r = 0;
            for (int b = 0; b < L; b++) r += (se[b] < my);
            ord[r] = a;
        }
        __syncthreads();
    }
    float aq = 0.0f, m0 = 0.0f, m1 = 0.0f, m2 = 0.0f;
    for (int a = 0; a < L; a++) {
        int slot = s0 + (srt ? ord[a] : a);
        int j = g_js[slot];
        float d0 = g_dir[3 * slot + 0];
        float d1 = g_dir[3 * slot + 1];
        float d2 = g_dir[3 * slot + 2];
        size_t fbx = (size_t)slot * 384;
        float fq = __half2float(g_filth[fbx + f]);
        float fR = __half2float(g_filth[fbx + 128 + f]);
        float fM = __half2float(g_filth[fbx + 256 + f]);
        size_t xb = (size_t)j * 384;
        float xq = __half2float(g_xh[xb + f]);
        float xR = __half2float(g_xh[xb + 128 + f]);
        float xM = __half2float(g_xh[xb + 256 + f]);
        float mj0 = g_muA[xb + f];
        float mj1 = g_muA[xb + 128 + f];
        float mj2 = g_muA[xb + 256 + f];
        aq += fq * xq;
        float tR = fR * xR, tM = fM * xM;
        m0 += tR * d0 + tM * mj0;
        m1 += tR * d1 + tM * mj1;
        m2 += tR * d2 + tM * mj2;
    }
    size_t mb_ = (size_t)i * 384;
    g_q[(size_t)i * 128 + f] += aq;
    float b0 = g_muA[mb_ + f] + m0;
    float b1 = g_muA[mb_ + 128 + f] + m1;
    float b2 = g_muA[mb_ + 256 + f] + m2;
    g_muB[mb_ + f] = b0;
    g_muB[mb_ + 128 + f] = b1;
    g_muB[mb_ + 256 + f] = b2;
    size_t hb = (size_t)i * 768;
    __half h0 = __float2half(b0);
    __half h1 = __float2half(b1);
    __half h2 = __float2half(b2);
    g_muBhl[hb + f] = h0;
    g_muBhl[hb + 128 + f] = __float2half(b0 - __half2float(h0));
    g_muBhl[hb + 256 + f] = h1;
    g_muBhl[hb + 384 + f] = __float2half(b1 - __half2float(h1));
    g_muBhl[hb + 512 + f] = h2;
    g_muBhl[hb + 640 + f] = __float2half(b2 - __half2float(h2));
}

// ---------------- mixing elementwise ----------------
__global__ void k_ctx() {
    int n = blockIdx.x;
    int f = threadIdx.x;
    size_t mmb = (size_t)n * 768;
    float v0 = g_mm[mmb + f];
    float v1 = g_mm[mmb + 256 + f];
    float v2 = g_mm[mmb + 512 + f];
    float w0 = g_mm[mmb + 128 + f];
    float w1 = g_mm[mmb + 384 + f];
    float w2 = g_mm[mmb + 640 + f];
    float vn = sqrtf(v0 * v0 + v1 * v1 + v2 * v2 + 1e-8f);
    float s = v0 * w0 + v1 * w1 + v2 * w2;
    float qv = g_q[(size_t)n * 128 + f];
    size_t cb = (size_t)n * 512;
    __half qh = __float2half(qv);
    __half vh = __float2half(vn);
    g_ctxhl[cb + f] = qh;
    g_ctxhl[cb + 128 + f] = vh;
    g_ctxhl[cb + 256 + f] = __float2half(qv - __half2float(qh));
    g_ctxhl[cb + 384 + f] = __float2half(vn - __half2float(vh));
    g_s[(size_t)n * 128 + f] = s;
}

__global__ void k_update() {
    int n = blockIdx.x;
    int f = threadIdx.x;
    size_t xb = (size_t)n * 384;
    float dq  = g_x[xb + f];
    float dmc = g_x[xb + 128 + f];
    float dqm = g_x[xb + 256 + f];
    float qn = g_q[(size_t)n * 128 + f] + dq + dqm * g_s[(size_t)n * 128 + f];
    g_q[(size_t)n * 128 + f] = qn;
    __half qh = __float2half(qn);
    g_qhl[(size_t)n * 256 + f] = qh;
    g_qhl[(size_t)n * 256 + 128 + f] = __float2half(qn - __half2float(qh));
    size_t mmb = (size_t)n * 768;
    g_muA[xb + f]       = g_muB[xb + f]       + dmc * g_mm[mmb + 128 + f];
    g_muA[xb + 128 + f] = g_muB[xb + 128 + f] + dmc * g_mm[mmb + 384 + f];
    g_muA[xb + 256 + f] = g_muB[xb + 256 + f] + dmc * g_mm[mmb + 640 + f];
}

// ---------------- launcher ----------------
extern "C" void kernel_launch(void* const* d_in, const int* in_sizes, int n_in,
                              void* d_out, int out_size) {
    const int*   z     = (const int*)d_in[0];
    const float* pos   = (const float*)d_in[1];
    const int*   idx_i = (const int*)d_in[2];
    const int*   idx_j = (const int*)d_in[3];
    const float* emb   = (const float*)d_in[4];
    const float* fW    = (const float*)d_in[5];
    const float* fb    = (const float*)d_in[6];
    const float* iW1   = (const float*)d_in[7];
    const float* ib1   = (const float*)d_in[8];
    const float* iW2   = (const float*)d_in[9];
    const float* ib2   = (const float*)d_in[10];
    const float* mWmix = (const float*)d_in[11];
    const float* mW1   = (const float*)d_in[12];
    const float* mb1   = (const float*)d_in[13];
    const float* mW2   = (const float*)d_in[14];
    const float* mb2   = (const float*)d_in[15];
    float* out = (float*)d_out;

    cudaFuncSetAttribute(k_wgemm, cudaFuncAttributeMaxDynamicSharedMemorySize, SMEM_WG);

    void *p_cnt, *p_muA, *p_q, *p_x, *p_xh, *p_mm, *p_filth;
    void *p_qhl, *p_hhl, *p_ctxhl, *p_muBhl, *p_phiHL, *p_fWXhl;
    void *p_WT1, *p_WT2, *p_WTmix, *p_WTm1, *p_WTm2;
    cudaGetSymbolAddress(&p_cnt, g_cnt);
    cudaGetSymbolAddress(&p_muA, g_muA);
    cudaGetSymbolAddress(&p_q, g_q);
    cudaGetSymbolAddress(&p_x, g_x);
    cudaGetSymbolAddress(&p_xh, g_xh);
    cudaGetSymbolAddress(&p_mm, g_mm);
    cudaGetSymbolAddress(&p_filth, g_filth);
    cudaGetSymbolAddress(&p_qhl, g_qhl);
    cudaGetSymbolAddress(&p_hhl, g_hhl);
    cudaGetSymbolAddress(&p_ctxhl, g_ctxhl);
    cudaGetSymbolAddress(&p_muBhl, g_muBhl);
    cudaGetSymbolAddress(&p_phiHL, g_phiHL);
    cudaGetSymbolAddress(&p_fWXhl, g_fWXhl);
    cudaGetSymbolAddress(&p_WT1, g_WT1);
    cudaGetSymbolAddress(&p_WT2, g_WT2);
    cudaGetSymbolAddress(&p_WTmix, g_WTmix);
    cudaGetSymbolAddress(&p_WTm1, g_WTm1);
    cudaGetSymbolAddress(&p_WTm2, g_WTm2);

    const __half* qhl = (const __half*)p_qhl;
    const __half* hhl = (const __half*)p_hhl;
    const __half* ctxhl = (const __half*)p_ctxhl;
    const __half* muBhl = (const __half*)p_muBhl;
    const __half* phiHL = (const __half*)p_phiHL;

    int ga = (NA + 127) / 128;       // 196
    int gm = (NA * 3 + 127) / 128;   // 586
    int ge = (NE + 127) / 128;       // 1563

    // ---- prep, ordered so the flagship GEMM is launch #6 (ncu -s 5 -c 1) ----
    cudaMemsetAsync(p_cnt, 0, NA * sizeof(int));                       // 1
    cudaMemsetAsync(p_muA, 0, (size_t)NA * 384 * sizeof(float));       // 2
    k_init_q<<<NA, 128>>>(z, emb);                                     // 3
    k_wsplit<<<dim3((128 * 128 + 255) / 256, 3), 256>>>(iW1, (__half*)p_WT1, 128, 128);   // 4
    k_wsplit<<<dim3((128 * 384 + 255) / 256, 3), 256>>>(iW2, (__half*)p_WT2, 128, 384);   // 5
    // H1(t=0): launch #6 -> profiled
    k_wgemm<<<dim3(ga, 1), 256, SMEM_WG>>>(
        qhl, (const __half*)p_WT1, ib1, nullptr, (__half*)p_hhl, NA, 256, 128, 1, 1);
    k_wsplit<<<dim3((128 * 256 + 255) / 256, 3), 256>>>(mWmix, (__half*)p_WTmix, 128, 256);
    k_wsplit<<<dim3((256 * 128 + 255) / 256, 3), 256>>>(mW1, (__half*)p_WTm1, 256, 128);
    k_wsplit<<<dim3((128 * 384 + 255) / 256, 3), 256>>>(mW2, (__half*)p_WTm2, 128, 384);
    k_fwx<<<(1152 + 127) / 128, 128>>>(fW, fb);
    k_count<<<(NE + 255) / 256, 256>>>(idx_i);
    k_scan<<<1, 1024>>>();
    k_build<<<(NE + 127) / 128, 128>>>(pos, idx_i, idx_j);

    for (int t = 0; t < 3; t++) {
        if (t > 0) {
            k_wgemm<<<dim3(ga, 1), 256, SMEM_WG>>>(
                qhl, (const __half*)p_WT1 + (size_t)t * 128 * 256,
                ib1 + t * 128, nullptr, (__half*)p_hhl, NA, 256, 128, 1, 1);
        }
        // X = H1 @ iW2 + ib2 -> g_xh (fp16 plain)
        k_wgemm<<<dim3(ga, 3), 256, SMEM_WG>>>(
            hhl, (const __half*)p_WT2 + (size_t)t * 384 * 256,
            ib2 + t * 384, nullptr, (__half*)p_xh, NA, 256, 384, 2, 0);
        // FILT = phi' @ fWX'^T -> g_filth (fp16 plain)
        k_wgemm<<<dim3(ge, 3), 256, SMEM_WG>>>(
            phiHL, (const __half*)p_fWXhl + (size_t)t * 384 * 64,
            nullptr, nullptr, (__half*)p_filth, NE, 64, 384, 2, 0);
        // edge aggregation
        k_edge<<<NA, 128>>>();
        // MUMIX = muB @ mWmix -> g_mm (fp32)
        k_wgemm<<<dim3(gm, 2), 256, SMEM_WG>>>(
            muBhl, (const __half*)p_WTmix + (size_t)t * 256 * 256,
            nullptr, (float*)p_mm, nullptr, NA * 3, 256, 256, 0, 0);
        k_ctx<<<NA, 128>>>();
        // H2 = silu(ctx @ mW1 + mb1) -> hhl   (K=512 packed)
        k_wgemm<<<dim3(ga, 1), 256, SMEM_WG>>>(
            ctxhl, (const __half*)p_WTm1 + (size_t)t * 128 * 512,
            mb1 + t * 128, nullptr, (__half*)p_hhl, NA, 512, 128, 1, 1);
        // X2 = H2 @ mW2 + mb2 -> g_x (fp32)
        k_wgemm<<<dim3(ga, 3), 256, SMEM_WG>>>(
            hhl, (const __half*)p_WTm2 + (size_t)t * 384 * 256,
            mb2 + t * 384, (float*)p_x, nullptr, NA, 256, 384, 0, 0);
        k_update<<<NA, 128>>>();
    }

    cudaMemcpyAsync(out, p_q, (size_t)NA * 128 * sizeof(float), cudaMemcpyDeviceToDevice);
    cudaMemcpyAsync(out + (size_t)NA * 128, p_muA, (size_t)NA * 384 * sizeof(float),
                    cudaMemcpyDeviceToDevice);
}